// round 12
// baseline (speedup 1.0000x reference)
#include <cuda_runtime.h>

#define FULLMASK 0xffffffffu
#define TB 148      // tail blocks (one per SM, co-resident)
#define TT 512      // tail threads
#define TAIL_SMALL 16  // blocks that survive past the first tail barrier

// ---------------- scratch (__device__ globals; no allocation allowed) ----------------
__device__ __align__(16) unsigned g_X1[6*784*40];      // packed bip(image, rm_in1)
__device__ __align__(16) unsigned g_W1[6*25*40];       // packed bip(w1, rm_k1)
__device__ __align__(16) unsigned g_W2[16*6*25*40];    // packed bip(w2, rm_k2)
__device__ __align__(16) unsigned g_X2[16*6*144*40];   // packed bip(p1norm, rm_in2)
__device__ __align__(16) unsigned g_SW3[120*256*40];   // [m][n][40]
__device__ __align__(16) unsigned g_SW4[84*120*40];    // [m][n][40]
__device__ __align__(16) unsigned g_SW5[10*84*40];     // [m][n][40]
__device__ __align__(16) unsigned g_X3[256*40];
__device__ __align__(16) unsigned g_X4[120*40];
__device__ __align__(16) unsigned g_X5[84*40];
__device__ int g_pos3[120];
__device__ int g_pos4[84];
__device__ int g_pos5[10];
__device__ float g_P1[864];       // pool1 (6,12,12) un-normalized
__device__ float g_P2[256];       // pool2 (16,4,4) un-normalized
__device__ float g_f1[120];       // relu(fc3) un-normalized
__device__ float g_f2[84];        // relu(fc4) un-normalized
__device__ unsigned g_mm[8];      // bit-punned nonneg float min/max pairs
__device__ unsigned g_arrive;     // barrier arrival counter (self-resetting)
__device__ unsigned g_gen2;       // barrier generation (monotonic across replays)

// ---------------- helpers ----------------

__device__ __forceinline__ int popc4(uint4 a, uint4 b) {
    return __popc(a.x ^ b.x) + __popc(a.y ^ b.y) + __popc(a.z ^ b.z) + __popc(a.w ^ b.w);
}

// Pack one bitstream row: 1280 floats -> 40 uint32 words. All 40 scalar loads
// hoisted before the ballot chain for max MLP. Natural bit layout everywhere.
__device__ __forceinline__ void pack_row(const float* __restrict__ src, float thr,
                                         unsigned* __restrict__ dst, int lane) {
    float v[40];
#pragma unroll
    for (int wd = 0; wd < 40; ++wd) v[wd] = src[wd*32 + lane];
#pragma unroll
    for (int wd = 0; wd < 40; wd += 4) {
        unsigned b0 = __ballot_sync(FULLMASK, thr > v[wd+0]);
        unsigned b1 = __ballot_sync(FULLMASK, thr > v[wd+1]);
        unsigned b2 = __ballot_sync(FULLMASK, thr > v[wd+2]);
        unsigned b3 = __ballot_sync(FULLMASK, thr > v[wd+3]);
        if (lane == 0) *reinterpret_cast<uint4*>(dst + wd) = make_uint4(b0, b1, b2, b3);
    }
}

__device__ __forceinline__ int pack_row_popc(const float* __restrict__ src, float thr, int lane) {
    float v[40];
#pragma unroll
    for (int wd = 0; wd < 40; ++wd) v[wd] = src[wd*32 + lane];
    int s = 0;
#pragma unroll
    for (int wd = 0; wd < 40; ++wd) s += __popc(__ballot_sync(FULLMASK, thr > v[wd]));
    return s;
}

__device__ __forceinline__ float thr_of(float v) {
    return __fmul_rn(__fadd_rn(v, 1.0f), 0.5f);
}

// Counter+gen grid barrier (R7-proven). nblocks = participants. gen grows
// monotonically across barriers AND graph replays; counter self-resets.
__device__ __forceinline__ void gbar(int nblocks) {
    __syncthreads();
    if (threadIdx.x == 0) {
        __threadfence();
        unsigned gen = *(volatile unsigned*)&g_gen2;
        if (atomicAdd(&g_arrive, 1u) == (unsigned)(nblocks - 1)) {
            atomicExch(&g_arrive, 0u);
            __threadfence();
            atomicAdd(&g_gen2, 1u);
        } else {
            while (*(volatile unsigned*)&g_gen2 == gen) __nanosleep(32);
        }
        __threadfence();
    }
    __syncthreads();
}

// ---------------- kernel 1: all static packing (241MB HBM) + g_mm init ----------------
__global__ void k_pack_static_all(const float* __restrict__ img, const float* __restrict__ w1,
                                  const float* __restrict__ w2,
                                  const float* __restrict__ wfc3, const float* __restrict__ wfc4,
                                  const float* __restrict__ wfc5,
                                  const float* __restrict__ bfc3, const float* __restrict__ bfc4,
                                  const float* __restrict__ bfc5,
                                  const float* __restrict__ rm_in1, const float* __restrict__ rm_k1,
                                  const float* __restrict__ rm_k2,
                                  const float* __restrict__ rm_w3, const float* __restrict__ rm_w4,
                                  const float* __restrict__ rm_w5,
                                  const float* __restrict__ rm_b3, const float* __restrict__ rm_b4,
                                  const float* __restrict__ rm_b5) {
    if (blockIdx.x == 0 && threadIdx.x < 8)
        g_mm[threadIdx.x] = (threadIdx.x & 1) ? 0u : 0x7f800000u;  // min=+inf, max=0

    int lane = threadIdx.x & 31;
    int gw = (blockIdx.x * blockDim.x + threadIdx.x) >> 5;
    int nw = (gridDim.x * blockDim.x) >> 5;
    const int RX1 = 6*784;               // 4704
    const int RW1 = RX1 + 6*25;          // 4854
    const int RW2 = RW1 + 16*6*25;       // 7254
    const int RS3 = RW2 + 256*120;       // 37974
    const int RS4 = RS3 + 120*84;        // 48054
    const int RS5 = RS4 + 84*10;         // 48894
    const int RB3 = RS5 + 120;
    const int RB4 = RB3 + 84;
    const int RB5 = RB4 + 10;            // 49108
    for (int row = gw; row < RB5; row += nw) {
        if (row < RX1) {
            pack_row(rm_in1 + (size_t)row * 1280, thr_of(img[row % 784]), g_X1 + row*40, lane);
        } else if (row < RW1) {
            int r = row - RX1;
            pack_row(rm_k1 + (size_t)r * 1280, thr_of(w1[r]), g_W1 + r*40, lane);
        } else if (row < RW2) {
            int r = row - RW1;
            pack_row(rm_k2 + (size_t)r * 1280, thr_of(w2[r]), g_W2 + r*40, lane);
        } else if (row < RS3) {
            int r = row - RW2; int n = r / 120, m = r % 120;   // rm_w3 is [n][m][l]
            pack_row(rm_w3 + (size_t)r * 1280, thr_of(wfc3[r]), g_SW3 + (m*256 + n)*40, lane);
        } else if (row < RS4) {
            int r = row - RS3; int n = r / 84, m = r % 84;
            pack_row(rm_w4 + (size_t)r * 1280, thr_of(wfc4[r]), g_SW4 + (m*120 + n)*40, lane);
        } else if (row < RS5) {
            int r = row - RS4; int n = r / 10, m = r % 10;
            pack_row(rm_w5 + (size_t)r * 1280, thr_of(wfc5[r]), g_SW5 + (m*84 + n)*40, lane);
        } else if (row < RB3) {
            int r = row - RS5;
            int s = pack_row_popc(rm_b3 + (size_t)r * 1280, thr_of(bfc3[r]), lane);
            if (lane == 0) g_pos3[r] = s;
        } else if (row < RB4) {
            int r = row - RB3;
            int s = pack_row_popc(rm_b4 + (size_t)r * 1280, thr_of(bfc4[r]), lane);
            if (lane == 0) g_pos4[r] = s;
        } else {
            int r = row - RB4;
            int s = pack_row_popc(rm_b5 + (size_t)r * 1280, thr_of(bfc5[r]), lane);
            if (lane == 0) g_pos5[r] = s;
        }
    }
}

// ---------------- kernel 2: conv1 + pool1 fused. warp = pool cell (4 windows). ----------------
__global__ void k_conv1pool1(const float* __restrict__ b1) {   // <<<108,256>>> = 864 warps
    int lane = threadIdx.x & 31;
    int gw = (blockIdx.x * blockDim.x + threadIdx.x) >> 5;     // 0..863 = pool cell
    int o = gw / 144, rem = gw % 144, pr = rem / 12, pc = rem % 12;
    const uint4* xb = reinterpret_cast<const uint4*>(g_X1 + o*784*40);
    const uint4* wb = reinterpret_cast<const uint4*>(g_W1 + o*25*40);
    float bo = b1[o];
    float m = 0.0f;
#pragma unroll
    for (int win = 0; win < 4; ++win) {
        int r = 2*pr + (win >> 1), c = 2*pc + (win & 1);
        int ham = 0;
        for (int q = lane; q < 250; q += 32) {        // (tap k, quad) flattened: 25*10
            int k = q / 10, quad = q - 10*k;
            int n = (r + k/5)*28 + (c + k%5);
            ham += popc4(xb[n*10 + quad], wb[k*10 + quad]);
        }
        ham = __reduce_add_sync(FULLMASK, ham);
        float cnt = (float)(32000 - ham);
        float q2 = __fmul_rn(cnt, (1.0f/32000.0f));
        float y = __fsub_rn(__fmul_rn(2.0f, q2), 1.0f);
        float v = fmaxf(__fadd_rn(__fmul_rn(y, 25.0f), bo), 0.0f);
        m = fmaxf(m, v);
    }
    if (lane == 0) {
        g_P1[gw] = m;
        atomicMin(&g_mm[0], __float_as_uint(m));
        atomicMax(&g_mm[1], __float_as_uint(m));
    }
}

// ---------------- kernel 3: pack X2 (71MB rm_in2) ----------------
__global__ void k_pack_X2(const float* __restrict__ rm_in2) {  // <<<1728,256>>> = 13824 warps
    int lane = threadIdx.x & 31;
    int row = (blockIdx.x * blockDim.x + threadIdx.x) >> 5;    // 0..13823
    float mn = __uint_as_float(g_mm[0]);
    float mx = __uint_as_float(g_mm[1]);
    float den = mx - mn;
    float p = g_P1[row % 864];                                 // row=(o*6+i)*144+n; %864 = i*144+n
    float pv = __fdiv_rn(p - mn, den);                         // norm01 (runtime denom: true div)
    pack_row(rm_in2 + (size_t)row * 1280, thr_of(pv), g_X2 + row*40, lane);
}

// ---------------- kernel 4: persistent tail (conv2+pool2 -> ... -> fc5) ----------------
__global__ void __launch_bounds__(TT, 1) k_tail(
    const float* __restrict__ b2,
    const float* __restrict__ rm_x3, const float* __restrict__ rm_x4,
    const float* __restrict__ rm_x5, float* __restrict__ out)
{
    __shared__ float shf[16];
    const int t = threadIdx.x;
    const int lane = t & 31;
    const int wid = t >> 5;
    const int b = blockIdx.x;
    const int gw = b * 16 + wid;             // global warp within surviving 16 blocks

    // ---- Phase A: conv2 + pool2 over ALL 148 blocks. Block b owns cells
    //      [b*256/148, (b+1)*256/148) (1-2 cells); warp = (local cell, window).
    {
        int cstart = (b * 256) / TB;
        int cend = ((b + 1) * 256) / TB;
        int lc = wid >> 2;                   // local cell 0..3 (only <count used)
        int cellIdx = cstart + lc;
        if (cellIdx < cend) {
            int o = cellIdx >> 4, rem = cellIdx & 15, pr = rem >> 2, pc = rem & 3;
            int win = wid & 3;
            int r = 2*pr + (win >> 1), c = 2*pc + (win & 1);
            const uint4* xb = reinterpret_cast<const uint4*>(g_X2 + o*6*144*40);
            const uint4* wb = reinterpret_cast<const uint4*>(g_W2 + o*6*25*40);
            int ham = 0;
#pragma unroll
            for (int i = 0; i < 6; ++i) {
                const uint4* xi = xb + i*144*10;
                const uint4* wi = wb + i*25*10;
                for (int q = lane; q < 250; q += 32) {
                    int k = q / 10, quad = q - 10*k;
                    int n = (r + k/5)*12 + (c + k%5);
                    ham += popc4(xi[n*10 + quad], wi[k*10 + quad]);
                }
            }
            ham = __reduce_add_sync(FULLMASK, ham);
            if (lane == 0) {
                float cnt = (float)(192000 - ham);
                float q = __fmul_rn(cnt, (1.0f/192000.0f));
                float y = __fsub_rn(__fmul_rn(2.0f, q), 1.0f);
                float v = __fadd_rn(__fmul_rn(y, 150.0f), b2[o]);
                shf[wid] = fmaxf(v, 0.0f);
            }
        }
        __syncthreads();
        int count = ((b + 1) * 256) / TB - (b * 256) / TB;
        if (t < count) {
            int ci = (b * 256) / TB + t;
            float m = fmaxf(fmaxf(shf[t*4+0], shf[t*4+1]), fmaxf(shf[t*4+2], shf[t*4+3]));
            g_P2[ci] = m;
            atomicMin(&g_mm[2], __float_as_uint(m));
            atomicMax(&g_mm[3], __float_as_uint(m));
        }
    }
    gbar(TB);

    // Only TAIL_SMALL blocks continue; the rest free their SMs.
    if (b >= TAIL_SMALL) return;

    // ---- Phase B: pack X3 (256 rows = exactly 16 blocks x 16 warps)
    {
        float mn = __uint_as_float(__ldcg(&g_mm[2]));
        float mx = __uint_as_float(__ldcg(&g_mm[3]));
        float den = mx - mn;
        float pv = __fdiv_rn(__ldcg(&g_P2[gw]) - mn, den);
        pack_row(rm_x3 + (size_t)gw * 1280, thr_of(pv), g_X3 + gw*40, lane);
    }
    gbar(TAIL_SMALL);

    // ---- Phase C: fc3 (120 warp-outputs)
    if (gw < 120) {
        int h = 0;
        for (int n = lane; n < 256; n += 32) {
            const uint4* xr = reinterpret_cast<const uint4*>(g_X3 + n*40);
            const uint4* sr = reinterpret_cast<const uint4*>(g_SW3 + (gw*256 + n)*40);
#pragma unroll
            for (int q = 0; q < 10; ++q) h += popc4(xr[q], sr[q]);
        }
        h = __reduce_add_sync(FULLMASK, h);
        if (lane == 0) {
            float cnt = (float)(327680 - h + __ldcg(&g_pos3[gw]));   // 256*1280 - H + pos
            float q = __fmul_rn(cnt, (1.0f/328960.0f));              // 257*1280
            float o3 = __fmul_rn(__fsub_rn(__fmul_rn(2.0f, q), 1.0f), 257.0f);
            float rv = fmaxf(o3, 0.0f);
            g_f1[gw] = rv;
            atomicMin(&g_mm[4], __float_as_uint(rv));
            atomicMax(&g_mm[5], __float_as_uint(rv));
        }
    }
    gbar(TAIL_SMALL);

    // ---- Phase D: pack X4 (120 rows)
    if (gw < 120) {
        float mn = __uint_as_float(__ldcg(&g_mm[4]));
        float mx = __uint_as_float(__ldcg(&g_mm[5]));
        float den = mx - mn;
        float pv = __fdiv_rn(__ldcg(&g_f1[gw]) - mn, den);
        pack_row(rm_x4 + (size_t)gw * 1280, thr_of(pv), g_X4 + gw*40, lane);
    }
    gbar(TAIL_SMALL);

    // ---- Phase E: fc4 (84 warp-outputs)
    if (gw < 84) {
        int h = 0;
        for (int n = lane; n < 120; n += 32) {
            const uint4* xr = reinterpret_cast<const uint4*>(g_X4 + n*40);
            const uint4* sr = reinterpret_cast<const uint4*>(g_SW4 + (gw*120 + n)*40);
#pragma unroll
            for (int q = 0; q < 10; ++q) h += popc4(xr[q], sr[q]);
        }
        h = __reduce_add_sync(FULLMASK, h);
        if (lane == 0) {
            float cnt = (float)(153600 - h + __ldcg(&g_pos4[gw]));   // 120*1280 - H + pos
            float q = __fmul_rn(cnt, (1.0f/154880.0f));              // 121*1280
            float o4 = __fmul_rn(__fsub_rn(__fmul_rn(2.0f, q), 1.0f), 121.0f);
            float rv = fmaxf(o4, 0.0f);
            g_f2[gw] = rv;
            atomicMin(&g_mm[6], __float_as_uint(rv));
            atomicMax(&g_mm[7], __float_as_uint(rv));
        }
    }
    gbar(TAIL_SMALL);

    // ---- Phase F: pack X5 (84 rows)
    if (gw < 84) {
        float mn = __uint_as_float(__ldcg(&g_mm[6]));
        float mx = __uint_as_float(__ldcg(&g_mm[7]));
        float den = mx - mn;
        float pv = __fdiv_rn(__ldcg(&g_f2[gw]) - mn, den);
        pack_row(rm_x5 + (size_t)gw * 1280, thr_of(pv), g_X5 + gw*40, lane);
    }
    gbar(TAIL_SMALL);

    // ---- Phase G: fc5 (10 warp-outputs)
    if (gw < 10) {
        int h = 0;
        for (int n = lane; n < 84; n += 32) {
            const uint4* xr = reinterpret_cast<const uint4*>(g_X5 + n*40);
            const uint4* sr = reinterpret_cast<const uint4*>(g_SW5 + (gw*84 + n)*40);
#pragma unroll
            for (int q = 0; q < 10; ++q) h += popc4(xr[q], sr[q]);
        }
        h = __reduce_add_sync(FULLMASK, h);
        if (lane == 0) {
            float cnt = (float)(107520 - h + __ldcg(&g_pos5[gw]));   // 84*1280 - H + pos
            float q = __fmul_rn(cnt, (1.0f/108800.0f));              // 85*1280
            out[gw] = __fmul_rn(__fsub_rn(__fmul_rn(2.0f, q), 1.0f), 85.0f);
        }
    }
}

// ---------------- launch ----------------
extern "C" void kernel_launch(void* const* d_in, const int* in_sizes, int n_in,
                              void* d_out, int out_size) {
    const float* img    = (const float*)d_in[0];
    const float* w1     = (const float*)d_in[1];
    const float* b1     = (const float*)d_in[2];
    const float* w2     = (const float*)d_in[3];
    const float* b2     = (const float*)d_in[4];
    const float* wfc3   = (const float*)d_in[5];
    const float* bfc3   = (const float*)d_in[6];
    const float* wfc4   = (const float*)d_in[7];
    const float* bfc4   = (const float*)d_in[8];
    const float* wfc5   = (const float*)d_in[9];
    const float* bfc5   = (const float*)d_in[10];
    const float* rm_in1 = (const float*)d_in[11];
    const float* rm_k1  = (const float*)d_in[12];
    const float* rm_in2 = (const float*)d_in[13];
    const float* rm_k2  = (const float*)d_in[14];
    const float* rm_x3  = (const float*)d_in[15];
    const float* rm_w3  = (const float*)d_in[16];
    const float* rm_b3  = (const float*)d_in[17];
    const float* rm_x4  = (const float*)d_in[18];
    const float* rm_w4  = (const float*)d_in[19];
    const float* rm_b4  = (const float*)d_in[20];
    const float* rm_x5  = (const float*)d_in[21];
    const float* rm_w5  = (const float*)d_in[22];
    const float* rm_b5  = (const float*)d_in[23];
    float* out = (float*)d_out;

    k_pack_static_all<<<2048, 256>>>(img, w1, w2, wfc3, wfc4, wfc5, bfc3, bfc4, bfc5,
                                     rm_in1, rm_k1, rm_k2, rm_w3, rm_w4, rm_w5,
                                     rm_b3, rm_b4, rm_b5);
    k_conv1pool1<<<108, 256>>>(b1);
    k_pack_X2<<<1728, 256>>>(rm_in2);
    k_tail<<<TB, TT>>>(b2, rm_x3, rm_x4, rm_x5, out);
}

// round 13
// speedup vs baseline: 1.1490x; 1.1490x over previous
#include <cuda_runtime.h>

#define FULLMASK 0xffffffffu
#define FB 32       // finisher blocks
#define FT 512      // finisher threads

// ---------------- scratch (__device__ globals; no allocation allowed) ----------------
__device__ __align__(16) unsigned g_X1[6*784*40];      // packed bip(image, rm_in1)
__device__ __align__(16) unsigned g_W1[6*25*40];       // packed bip(w1, rm_k1)
__device__ __align__(16) unsigned g_W2[16*6*25*40];    // packed bip(w2, rm_k2)
__device__ __align__(16) unsigned g_X2[16*6*144*40];   // packed bip(p1norm, rm_in2)
__device__ __align__(16) unsigned g_SW3[120*256*40];   // [m][n][40]
__device__ __align__(16) unsigned g_SW4[84*120*40];    // [m][n][40]
__device__ __align__(16) unsigned g_SW5[10*84*40];     // [m][n][40]
__device__ __align__(16) unsigned g_X3[256*40];
__device__ __align__(16) unsigned g_X4[120*40];
__device__ __align__(16) unsigned g_X5[84*40];
__device__ int g_pos3[120];
__device__ int g_pos4[84];
__device__ int g_pos5[10];
__device__ float g_P1[864];       // pool1 (6,12,12) un-normalized
__device__ float g_P2[256];       // pool2 (16,4,4) un-normalized
__device__ float g_f1[120];       // relu(fc3) un-normalized
__device__ float g_f2[84];        // relu(fc4) un-normalized
__device__ unsigned g_mm[8];      // bit-punned nonneg float min/max pairs
__device__ unsigned g_arrive;     // barrier arrival counter (self-resetting)
__device__ unsigned g_gen2;       // barrier generation (monotonic across replays)

// ---------------- helpers ----------------

__device__ __forceinline__ int popc4(uint4 a, uint4 b) {
    return __popc(a.x ^ b.x) + __popc(a.y ^ b.y) + __popc(a.z ^ b.z) + __popc(a.w ^ b.w);
}

// Pack one bitstream row: 1280 floats -> 40 uint32 words. All 40 scalar loads
// hoisted before the ballot chain for max MLP. Natural bit layout everywhere.
__device__ __forceinline__ void pack_row(const float* __restrict__ src, float thr,
                                         unsigned* __restrict__ dst, int lane) {
    float v[40];
#pragma unroll
    for (int wd = 0; wd < 40; ++wd) v[wd] = src[wd*32 + lane];
#pragma unroll
    for (int wd = 0; wd < 40; wd += 4) {
        unsigned b0 = __ballot_sync(FULLMASK, thr > v[wd+0]);
        unsigned b1 = __ballot_sync(FULLMASK, thr > v[wd+1]);
        unsigned b2 = __ballot_sync(FULLMASK, thr > v[wd+2]);
        unsigned b3 = __ballot_sync(FULLMASK, thr > v[wd+3]);
        if (lane == 0) *reinterpret_cast<uint4*>(dst + wd) = make_uint4(b0, b1, b2, b3);
    }
}

__device__ __forceinline__ int pack_row_popc(const float* __restrict__ src, float thr, int lane) {
    float v[40];
#pragma unroll
    for (int wd = 0; wd < 40; ++wd) v[wd] = src[wd*32 + lane];
    int s = 0;
#pragma unroll
    for (int wd = 0; wd < 40; ++wd) s += __popc(__ballot_sync(FULLMASK, thr > v[wd]));
    return s;
}

__device__ __forceinline__ float thr_of(float v) {
    return __fmul_rn(__fadd_rn(v, 1.0f), 0.5f);
}

// Counter+gen grid barrier among `nblocks` co-resident blocks. gen grows
// monotonically across barriers AND graph replays; counter self-resets.
__device__ __forceinline__ void gbar(int nblocks) {
    __syncthreads();
    if (threadIdx.x == 0) {
        __threadfence();
        unsigned gen = *(volatile unsigned*)&g_gen2;
        if (atomicAdd(&g_arrive, 1u) == (unsigned)(nblocks - 1)) {
            atomicExch(&g_arrive, 0u);
            __threadfence();
            atomicAdd(&g_gen2, 1u);
        } else {
            while (*(volatile unsigned*)&g_gen2 == gen) __nanosleep(64);
        }
        __threadfence();
    }
    __syncthreads();
}

// ---------------- kernel 1: all static packing (241MB HBM) + g_mm init ----------------
__global__ void k_pack_static_all(const float* __restrict__ img, const float* __restrict__ w1,
                                  const float* __restrict__ w2,
                                  const float* __restrict__ wfc3, const float* __restrict__ wfc4,
                                  const float* __restrict__ wfc5,
                                  const float* __restrict__ bfc3, const float* __restrict__ bfc4,
                                  const float* __restrict__ bfc5,
                                  const float* __restrict__ rm_in1, const float* __restrict__ rm_k1,
                                  const float* __restrict__ rm_k2,
                                  const float* __restrict__ rm_w3, const float* __restrict__ rm_w4,
                                  const float* __restrict__ rm_w5,
                                  const float* __restrict__ rm_b3, const float* __restrict__ rm_b4,
                                  const float* __restrict__ rm_b5) {
    if (blockIdx.x == 0 && threadIdx.x < 8)
        g_mm[threadIdx.x] = (threadIdx.x & 1) ? 0u : 0x7f800000u;  // min=+inf, max=0

    int lane = threadIdx.x & 31;
    int gw = (blockIdx.x * blockDim.x + threadIdx.x) >> 5;
    int nw = (gridDim.x * blockDim.x) >> 5;
    const int RX1 = 6*784;               // 4704
    const int RW1 = RX1 + 6*25;          // 4854
    const int RW2 = RW1 + 16*6*25;       // 7254
    const int RS3 = RW2 + 256*120;       // 37974
    const int RS4 = RS3 + 120*84;        // 48054
    const int RS5 = RS4 + 84*10;         // 48894
    const int RB3 = RS5 + 120;
    const int RB4 = RB3 + 84;
    const int RB5 = RB4 + 10;            // 49108
    for (int row = gw; row < RB5; row += nw) {
        if (row < RX1) {
            pack_row(rm_in1 + (size_t)row * 1280, thr_of(img[row % 784]), g_X1 + row*40, lane);
        } else if (row < RW1) {
            int r = row - RX1;
            pack_row(rm_k1 + (size_t)r * 1280, thr_of(w1[r]), g_W1 + r*40, lane);
        } else if (row < RW2) {
            int r = row - RW1;
            pack_row(rm_k2 + (size_t)r * 1280, thr_of(w2[r]), g_W2 + r*40, lane);
        } else if (row < RS3) {
            int r = row - RW2; int n = r / 120, m = r % 120;   // rm_w3 is [n][m][l]
            pack_row(rm_w3 + (size_t)r * 1280, thr_of(wfc3[r]), g_SW3 + (m*256 + n)*40, lane);
        } else if (row < RS4) {
            int r = row - RS3; int n = r / 84, m = r % 84;
            pack_row(rm_w4 + (size_t)r * 1280, thr_of(wfc4[r]), g_SW4 + (m*120 + n)*40, lane);
        } else if (row < RS5) {
            int r = row - RS4; int n = r / 10, m = r % 10;
            pack_row(rm_w5 + (size_t)r * 1280, thr_of(wfc5[r]), g_SW5 + (m*84 + n)*40, lane);
        } else if (row < RB3) {
            int r = row - RS5;
            int s = pack_row_popc(rm_b3 + (size_t)r * 1280, thr_of(bfc3[r]), lane);
            if (lane == 0) g_pos3[r] = s;
        } else if (row < RB4) {
            int r = row - RB3;
            int s = pack_row_popc(rm_b4 + (size_t)r * 1280, thr_of(bfc4[r]), lane);
            if (lane == 0) g_pos4[r] = s;
        } else {
            int r = row - RB4;
            int s = pack_row_popc(rm_b5 + (size_t)r * 1280, thr_of(bfc5[r]), lane);
            if (lane == 0) g_pos5[r] = s;
        }
    }
}

// ---------------- kernel 2: conv1 + pool1 fused. warp = pool cell (4 windows). ----------------
__global__ void k_conv1pool1(const float* __restrict__ b1) {   // <<<108,256>>> = 864 warps
    int lane = threadIdx.x & 31;
    int gw = (blockIdx.x * blockDim.x + threadIdx.x) >> 5;     // 0..863 = pool cell
    int o = gw / 144, rem = gw % 144, pr = rem / 12, pc = rem % 12;
    const uint4* xb = reinterpret_cast<const uint4*>(g_X1 + o*784*40);
    const uint4* wb = reinterpret_cast<const uint4*>(g_W1 + o*25*40);
    float bo = b1[o];
    float m = 0.0f;
#pragma unroll
    for (int win = 0; win < 4; ++win) {
        int r = 2*pr + (win >> 1), c = 2*pc + (win & 1);
        int ham = 0;
        for (int q = lane; q < 250; q += 32) {        // (tap k, quad) flattened: 25*10
            int k = q / 10, quad = q - 10*k;
            int n = (r + k/5)*28 + (c + k%5);
            ham += popc4(xb[n*10 + quad], wb[k*10 + quad]);
        }
        ham = __reduce_add_sync(FULLMASK, ham);
        float cnt = (float)(32000 - ham);
        float q2 = __fmul_rn(cnt, (1.0f/32000.0f));
        float y = __fsub_rn(__fmul_rn(2.0f, q2), 1.0f);
        float v = fmaxf(__fadd_rn(__fmul_rn(y, 25.0f), bo), 0.0f);
        m = fmaxf(m, v);
    }
    if (lane == 0) {
        g_P1[gw] = m;
        atomicMin(&g_mm[0], __float_as_uint(m));
        atomicMax(&g_mm[1], __float_as_uint(m));
    }
}

// ---------------- kernel 3: pack X2 (71MB rm_in2) ----------------
__global__ void k_pack_X2(const float* __restrict__ rm_in2) {  // <<<1728,256>>> = 13824 warps
    int lane = threadIdx.x & 31;
    int row = (blockIdx.x * blockDim.x + threadIdx.x) >> 5;    // 0..13823
    float mn = __uint_as_float(g_mm[0]);
    float mx = __uint_as_float(g_mm[1]);
    float den = mx - mn;
    float p = g_P1[row % 864];                                 // row=(o*6+i)*144+n; %864 = i*144+n
    float pv = __fdiv_rn(p - mn, den);                         // norm01 (runtime denom: true div)
    pack_row(rm_in2 + (size_t)row * 1280, thr_of(pv), g_X2 + row*40, lane);
}

// ---------------- kernel 4: conv2 + pool2 (standalone; kernel boundary = sync) ----------------
__global__ void k_conv2pool2(const float* __restrict__ b2) {   // <<<64,512>>>
    __shared__ float shf[16];
    int t = threadIdx.x;
    int lane = t & 31;
    int wid = t >> 5;                     // 0..15
    int cellIdx = blockIdx.x * 4 + (wid >> 2);   // 0..255
    int o = cellIdx >> 4, rem = cellIdx & 15, pr = rem >> 2, pc = rem & 3;
    int win = wid & 3;
    int r = 2*pr + (win >> 1), c = 2*pc + (win & 1);
    const uint4* xb = reinterpret_cast<const uint4*>(g_X2 + o*6*144*40);
    const uint4* wb = reinterpret_cast<const uint4*>(g_W2 + o*6*25*40);
    int ham = 0;
#pragma unroll
    for (int i = 0; i < 6; ++i) {
        const uint4* xi = xb + i*144*10;
        const uint4* wi = wb + i*25*10;
        for (int q = lane; q < 250; q += 32) {
            int k = q / 10, quad = q - 10*k;
            int n = (r + k/5)*12 + (c + k%5);
            ham += popc4(xi[n*10 + quad], wi[k*10 + quad]);
        }
    }
    ham = __reduce_add_sync(FULLMASK, ham);
    if (lane == 0) {
        float cnt = (float)(192000 - ham);
        float q = __fmul_rn(cnt, (1.0f/192000.0f));
        float y = __fsub_rn(__fmul_rn(2.0f, q), 1.0f);
        float v = __fadd_rn(__fmul_rn(y, 150.0f), b2[o]);
        shf[wid] = fmaxf(v, 0.0f);
    }
    __syncthreads();
    if (t < 4) {
        int ci = blockIdx.x * 4 + t;
        float m = fmaxf(fmaxf(shf[t*4+0], shf[t*4+1]), fmaxf(shf[t*4+2], shf[t*4+3]));
        g_P2[ci] = m;
        atomicMin(&g_mm[2], __float_as_uint(m));
        atomicMax(&g_mm[3], __float_as_uint(m));
    }
}

// ---------------- kernel 5: finisher (packX3 -> fc3 -> packX4 -> fc4 -> packX5 -> fc5) ----------------
// 32 blocks x 512 threads; work strided by block so FC DRAM pulls spread over all 32 SMs.
__global__ void __launch_bounds__(FT, 1) k_finish(
    const float* __restrict__ rm_x3, const float* __restrict__ rm_x4,
    const float* __restrict__ rm_x5, float* __restrict__ out)
{
    const int t = threadIdx.x;
    const int lane = t & 31;
    const int wid = t >> 5;               // 0..15
    const int b = blockIdx.x;             // 0..31

    // ---- Phase B: pack X3 — 256 rows = 32 blocks x warps 0..7, row = wid*32 + b
    if (wid < 8) {
        int row = wid*32 + b;
        float mn = __uint_as_float(__ldcg(&g_mm[2]));
        float mx = __uint_as_float(__ldcg(&g_mm[3]));
        float den = mx - mn;
        float pv = __fdiv_rn(__ldcg(&g_P2[row]) - mn, den);
        pack_row(rm_x3 + (size_t)row * 1280, thr_of(pv), g_X3 + row*40, lane);
    }
    gbar(FB);

    // ---- Phase C: fc3 — 120 outputs, m = wid*32 + b (wid<4, guard m<120)
    if (wid < 4) {
        int m = wid*32 + b;
        if (m < 120) {
            int h = 0;
            for (int n = lane; n < 256; n += 32) {
                const uint4* xr = reinterpret_cast<const uint4*>(g_X3 + n*40);
                const uint4* sr = reinterpret_cast<const uint4*>(g_SW3 + (m*256 + n)*40);
#pragma unroll
                for (int q = 0; q < 10; ++q) h += popc4(xr[q], sr[q]);
            }
            h = __reduce_add_sync(FULLMASK, h);
            if (lane == 0) {
                float cnt = (float)(327680 - h + __ldcg(&g_pos3[m]));   // 256*1280 - H + pos
                float q = __fmul_rn(cnt, (1.0f/328960.0f));             // 257*1280
                float o3 = __fmul_rn(__fsub_rn(__fmul_rn(2.0f, q), 1.0f), 257.0f);
                float rv = fmaxf(o3, 0.0f);
                g_f1[m] = rv;
                atomicMin(&g_mm[4], __float_as_uint(rv));
                atomicMax(&g_mm[5], __float_as_uint(rv));
            }
        }
    }
    gbar(FB);

    // ---- Phase D: pack X4 — 120 rows, row = wid*32 + b (wid<4, guard)
    if (wid < 4) {
        int row = wid*32 + b;
        if (row < 120) {
            float mn = __uint_as_float(__ldcg(&g_mm[4]));
            float mx = __uint_as_float(__ldcg(&g_mm[5]));
            float den = mx - mn;
            float pv = __fdiv_rn(__ldcg(&g_f1[row]) - mn, den);
            pack_row(rm_x4 + (size_t)row * 1280, thr_of(pv), g_X4 + row*40, lane);
        }
    }
    gbar(FB);

    // ---- Phase E: fc4 — 84 outputs, m = wid*32 + b (wid<3, guard m<84)
    if (wid < 3) {
        int m = wid*32 + b;
        if (m < 84) {
            int h = 0;
            for (int n = lane; n < 120; n += 32) {
                const uint4* xr = reinterpret_cast<const uint4*>(g_X4 + n*40);
                const uint4* sr = reinterpret_cast<const uint4*>(g_SW4 + (m*120 + n)*40);
#pragma unroll
                for (int q = 0; q < 10; ++q) h += popc4(xr[q], sr[q]);
            }
            h = __reduce_add_sync(FULLMASK, h);
            if (lane == 0) {
                float cnt = (float)(153600 - h + __ldcg(&g_pos4[m]));   // 120*1280 - H + pos
                float q = __fmul_rn(cnt, (1.0f/154880.0f));             // 121*1280
                float o4 = __fmul_rn(__fsub_rn(__fmul_rn(2.0f, q), 1.0f), 121.0f);
                float rv = fmaxf(o4, 0.0f);
                g_f2[m] = rv;
                atomicMin(&g_mm[6], __float_as_uint(rv));
                atomicMax(&g_mm[7], __float_as_uint(rv));
            }
        }
    }
    gbar(FB);

    // ---- Phase F: pack X5 — 84 rows, row = wid*32 + b (wid<3, guard)
    if (wid < 3) {
        int row = wid*32 + b;
        if (row < 84) {
            float mn = __uint_as_float(__ldcg(&g_mm[6]));
            float mx = __uint_as_float(__ldcg(&g_mm[7]));
            float den = mx - mn;
            float pv = __fdiv_rn(__ldcg(&g_f2[row]) - mn, den);
            pack_row(rm_x5 + (size_t)row * 1280, thr_of(pv), g_X5 + row*40, lane);
        }
    }
    gbar(FB);

    // ---- Phase G: fc5 — 10 outputs, m = b (warp 0 of blocks 0..9)
    if (wid == 0 && b < 10) {
        int m = b;
        int h = 0;
        for (int n = lane; n < 84; n += 32) {
            const uint4* xr = reinterpret_cast<const uint4*>(g_X5 + n*40);
            const uint4* sr = reinterpret_cast<const uint4*>(g_SW5 + (m*84 + n)*40);
#pragma unroll
            for (int q = 0; q < 10; ++q) h += popc4(xr[q], sr[q]);
        }
        h = __reduce_add_sync(FULLMASK, h);
        if (lane == 0) {
            float cnt = (float)(107520 - h + __ldcg(&g_pos5[m]));   // 84*1280 - H + pos
            float q = __fmul_rn(cnt, (1.0f/108800.0f));             // 85*1280
            out[m] = __fmul_rn(__fsub_rn(__fmul_rn(2.0f, q), 1.0f), 85.0f);
        }
    }
}

// ---------------- launch ----------------
extern "C" void kernel_launch(void* const* d_in, const int* in_sizes, int n_in,
                              void* d_out, int out_size) {
    const float* img    = (const float*)d_in[0];
    const float* w1     = (const float*)d_in[1];
    const float* b1     = (const float*)d_in[2];
    const float* w2     = (const float*)d_in[3];
    const float* b2     = (const float*)d_in[4];
    const float* wfc3   = (const float*)d_in[5];
    const float* bfc3   = (const float*)d_in[6];
    const float* wfc4   = (const float*)d_in[7];
    const float* bfc4   = (const float*)d_in[8];
    const float* wfc5   = (const float*)d_in[9];
    const float* bfc5   = (const float*)d_in[10];
    const float* rm_in1 = (const float*)d_in[11];
    const float* rm_k1  = (const float*)d_in[12];
    const float* rm_in2 = (const float*)d_in[13];
    const float* rm_k2  = (const float*)d_in[14];
    const float* rm_x3  = (const float*)d_in[15];
    const float* rm_w3  = (const float*)d_in[16];
    const float* rm_b3  = (const float*)d_in[17];
    const float* rm_x4  = (const float*)d_in[18];
    const float* rm_w4  = (const float*)d_in[19];
    const float* rm_b4  = (const float*)d_in[20];
    const float* rm_x5  = (const float*)d_in[21];
    const float* rm_w5  = (const float*)d_in[22];
    const float* rm_b5  = (const float*)d_in[23];
    float* out = (float*)d_out;

    k_pack_static_all<<<2048, 256>>>(img, w1, w2, wfc3, wfc4, wfc5, bfc3, bfc4, bfc5,
                                     rm_in1, rm_k1, rm_k2, rm_w3, rm_w4, rm_w5,
                                     rm_b3, rm_b4, rm_b5);
    k_conv1pool1<<<108, 256>>>(b1);
    k_pack_X2<<<1728, 256>>>(rm_in2);
    k_conv2pool2<<<64, 512>>>(b2);
    k_finish<<<FB, FT>>>(rm_x3, rm_x4, rm_x5, out);
}

// round 14
// speedup vs baseline: 1.3034x; 1.1344x over previous
#include <cuda_runtime.h>

#define FULLMASK 0xffffffffu
#define FB 32       // finisher blocks
#define FT 512      // finisher threads

// ---------------- scratch (__device__ globals; no allocation allowed) ----------------
__device__ __align__(16) unsigned g_X1[6*784*40];      // packed bip(image, rm_in1)
__device__ __align__(16) unsigned g_W1[6*25*40];       // packed bip(w1, rm_k1)
__device__ __align__(16) unsigned g_W2[16*6*25*40];    // packed bip(w2, rm_k2)
__device__ __align__(16) unsigned g_X2[16*6*144*40];   // packed bip(p1norm, rm_in2)
__device__ __align__(16) unsigned g_SW3[120*256*40];   // [m][n][40]
__device__ __align__(16) unsigned g_SW4[84*120*40];    // [m][n][40]
__device__ __align__(16) unsigned g_SW5[10*84*40];     // [m][n][40]
__device__ __align__(16) unsigned g_X3[256*40];
__device__ __align__(16) unsigned g_X4[120*40];
__device__ __align__(16) unsigned g_X5[84*40];
__device__ int g_pos3[120];
__device__ int g_pos4[84];
__device__ int g_pos5[10];
__device__ int g_c2h[1024];       // conv2 partial hamming sums (window-major o*64+r*8+c)
__device__ float g_P1[864];       // pool1 (6,12,12) un-normalized
__device__ float g_f1[120];       // relu(fc3) un-normalized
__device__ float g_f2[84];        // relu(fc4) un-normalized
__device__ unsigned g_mm[8];      // bit-punned nonneg float min/max pairs ([0,1]=pool1 [4,5]=fc3 [6,7]=fc4)
__device__ unsigned g_arrive;     // barrier arrival counter (self-resetting)
__device__ unsigned g_gen2;       // barrier generation (monotonic across replays)

// ---------------- helpers ----------------

__device__ __forceinline__ int popc4(uint4 a, uint4 b) {
    return __popc(a.x ^ b.x) + __popc(a.y ^ b.y) + __popc(a.z ^ b.z) + __popc(a.w ^ b.w);
}

// Pack one bitstream row: 1280 floats -> 40 uint32 words. All 40 scalar loads
// hoisted before the ballot chain for max MLP. Natural bit layout everywhere.
__device__ __forceinline__ void pack_row(const float* __restrict__ src, float thr,
                                         unsigned* __restrict__ dst, int lane) {
    float v[40];
#pragma unroll
    for (int wd = 0; wd < 40; ++wd) v[wd] = src[wd*32 + lane];
#pragma unroll
    for (int wd = 0; wd < 40; wd += 4) {
        unsigned b0 = __ballot_sync(FULLMASK, thr > v[wd+0]);
        unsigned b1 = __ballot_sync(FULLMASK, thr > v[wd+1]);
        unsigned b2 = __ballot_sync(FULLMASK, thr > v[wd+2]);
        unsigned b3 = __ballot_sync(FULLMASK, thr > v[wd+3]);
        if (lane == 0) *reinterpret_cast<uint4*>(dst + wd) = make_uint4(b0, b1, b2, b3);
    }
}

__device__ __forceinline__ int pack_row_popc(const float* __restrict__ src, float thr, int lane) {
    float v[40];
#pragma unroll
    for (int wd = 0; wd < 40; ++wd) v[wd] = src[wd*32 + lane];
    int s = 0;
#pragma unroll
    for (int wd = 0; wd < 40; ++wd) s += __popc(__ballot_sync(FULLMASK, thr > v[wd]));
    return s;
}

__device__ __forceinline__ float thr_of(float v) {
    return __fmul_rn(__fadd_rn(v, 1.0f), 0.5f);
}

// Counter+gen grid barrier among `nblocks` co-resident blocks. gen grows
// monotonically across barriers AND graph replays; counter self-resets.
__device__ __forceinline__ void gbar(int nblocks) {
    __syncthreads();
    if (threadIdx.x == 0) {
        __threadfence();
        unsigned gen = *(volatile unsigned*)&g_gen2;
        if (atomicAdd(&g_arrive, 1u) == (unsigned)(nblocks - 1)) {
            atomicExch(&g_arrive, 0u);
            __threadfence();
            atomicAdd(&g_gen2, 1u);
        } else {
            while (*(volatile unsigned*)&g_gen2 == gen) __nanosleep(64);
        }
        __threadfence();
    }
    __syncthreads();
}

// ---------------- kernel 1: all static packing (241MB HBM) + init ----------------
__global__ void k_pack_static_all(const float* __restrict__ img, const float* __restrict__ w1,
                                  const float* __restrict__ w2,
                                  const float* __restrict__ wfc3, const float* __restrict__ wfc4,
                                  const float* __restrict__ wfc5,
                                  const float* __restrict__ bfc3, const float* __restrict__ bfc4,
                                  const float* __restrict__ bfc5,
                                  const float* __restrict__ rm_in1, const float* __restrict__ rm_k1,
                                  const float* __restrict__ rm_k2,
                                  const float* __restrict__ rm_w3, const float* __restrict__ rm_w4,
                                  const float* __restrict__ rm_w5,
                                  const float* __restrict__ rm_b3, const float* __restrict__ rm_b4,
                                  const float* __restrict__ rm_b5) {
    if (blockIdx.x == 0 && threadIdx.x < 8)
        g_mm[threadIdx.x] = (threadIdx.x & 1) ? 0u : 0x7f800000u;  // min=+inf, max=0
    if (blockIdx.x == 1 && threadIdx.x < 256) {                    // zero conv2 partials (replay-safe)
        g_c2h[threadIdx.x] = 0;
        g_c2h[threadIdx.x + 256] = 0;
        g_c2h[threadIdx.x + 512] = 0;
        g_c2h[threadIdx.x + 768] = 0;
    }

    int lane = threadIdx.x & 31;
    int gw = (blockIdx.x * blockDim.x + threadIdx.x) >> 5;
    int nw = (gridDim.x * blockDim.x) >> 5;
    const int RX1 = 6*784;               // 4704
    const int RW1 = RX1 + 6*25;          // 4854
    const int RW2 = RW1 + 16*6*25;       // 7254
    const int RS3 = RW2 + 256*120;       // 37974
    const int RS4 = RS3 + 120*84;        // 48054
    const int RS5 = RS4 + 84*10;         // 48894
    const int RB3 = RS5 + 120;
    const int RB4 = RB3 + 84;
    const int RB5 = RB4 + 10;            // 49108
    for (int row = gw; row < RB5; row += nw) {
        if (row < RX1) {
            pack_row(rm_in1 + (size_t)row * 1280, thr_of(img[row % 784]), g_X1 + row*40, lane);
        } else if (row < RW1) {
            int r = row - RX1;
            pack_row(rm_k1 + (size_t)r * 1280, thr_of(w1[r]), g_W1 + r*40, lane);
        } else if (row < RW2) {
            int r = row - RW1;
            pack_row(rm_k2 + (size_t)r * 1280, thr_of(w2[r]), g_W2 + r*40, lane);
        } else if (row < RS3) {
            int r = row - RW2; int n = r / 120, m = r % 120;   // rm_w3 is [n][m][l]
            pack_row(rm_w3 + (size_t)r * 1280, thr_of(wfc3[r]), g_SW3 + (m*256 + n)*40, lane);
        } else if (row < RS4) {
            int r = row - RS3; int n = r / 84, m = r % 84;
            pack_row(rm_w4 + (size_t)r * 1280, thr_of(wfc4[r]), g_SW4 + (m*120 + n)*40, lane);
        } else if (row < RS5) {
            int r = row - RS4; int n = r / 10, m = r % 10;
            pack_row(rm_w5 + (size_t)r * 1280, thr_of(wfc5[r]), g_SW5 + (m*84 + n)*40, lane);
        } else if (row < RB3) {
            int r = row - RS5;
            int s = pack_row_popc(rm_b3 + (size_t)r * 1280, thr_of(bfc3[r]), lane);
            if (lane == 0) g_pos3[r] = s;
        } else if (row < RB4) {
            int r = row - RB3;
            int s = pack_row_popc(rm_b4 + (size_t)r * 1280, thr_of(bfc4[r]), lane);
            if (lane == 0) g_pos4[r] = s;
        } else {
            int r = row - RB4;
            int s = pack_row_popc(rm_b5 + (size_t)r * 1280, thr_of(bfc5[r]), lane);
            if (lane == 0) g_pos5[r] = s;
        }
    }
}

// ---------------- kernel 2: conv1 + pool1 fused. warp = pool cell (4 windows). ----------------
__global__ void k_conv1pool1(const float* __restrict__ b1) {   // <<<108,256>>> = 864 warps
    int lane = threadIdx.x & 31;
    int gw = (blockIdx.x * blockDim.x + threadIdx.x) >> 5;     // 0..863 = pool cell
    int o = gw / 144, rem = gw % 144, pr = rem / 12, pc = rem % 12;
    const uint4* xb = reinterpret_cast<const uint4*>(g_X1 + o*784*40);
    const uint4* wb = reinterpret_cast<const uint4*>(g_W1 + o*25*40);
    float bo = b1[o];
    float m = 0.0f;
#pragma unroll
    for (int win = 0; win < 4; ++win) {
        int r = 2*pr + (win >> 1), c = 2*pc + (win & 1);
        int ham = 0;
        for (int q = lane; q < 250; q += 32) {        // (tap k, quad) flattened: 25*10
            int k = q / 10, quad = q - 10*k;
            int n = (r + k/5)*28 + (c + k%5);
            ham += popc4(xb[n*10 + quad], wb[k*10 + quad]);
        }
        ham = __reduce_add_sync(FULLMASK, ham);
        float cnt = (float)(32000 - ham);
        float q2 = __fmul_rn(cnt, (1.0f/32000.0f));
        float y = __fsub_rn(__fmul_rn(2.0f, q2), 1.0f);
        float v = fmaxf(__fadd_rn(__fmul_rn(y, 25.0f), bo), 0.0f);
        m = fmaxf(m, v);
    }
    if (lane == 0) {
        g_P1[gw] = m;
        atomicMin(&g_mm[0], __float_as_uint(m));
        atomicMax(&g_mm[1], __float_as_uint(m));
    }
}

// ---------------- kernel 3: pack X2 (71MB rm_in2) ----------------
__global__ void k_pack_X2(const float* __restrict__ rm_in2) {  // <<<1728,256>>> = 13824 warps
    int lane = threadIdx.x & 31;
    int row = (blockIdx.x * blockDim.x + threadIdx.x) >> 5;    // 0..13823
    float mn = __uint_as_float(g_mm[0]);
    float mx = __uint_as_float(g_mm[1]);
    float den = mx - mn;
    float p = g_P1[row % 864];                                 // row=(o*6+i)*144+n; %864 = i*144+n
    float pv = __fdiv_rn(p - mn, den);                         // norm01 (runtime denom: true div)
    pack_row(rm_in2 + (size_t)row * 1280, thr_of(pv), g_X2 + row*40, lane);
}

// ---------------- kernel 4: conv2 partial hammings. warp = (window, channel). ----------------
// 1024 windows x 6 channels = 6144 warp-tasks over 768 blocks x 8 warps.
// All 16 loads per warp hoisted (predicated) -> full L2 latency hiding.
__global__ void k_conv2part() {   // <<<768,256>>>
    int lane = threadIdx.x & 31;
    int wid = threadIdx.x >> 5;
    int task = blockIdx.x * 8 + wid;          // 0..6143
    int w = task / 6;                         // window 0..1023
    int i = task - 6*w;                       // channel 0..5
    int o = w >> 6, rc = w & 63, r = rc >> 3, c = rc & 7;
    const uint4* xi = reinterpret_cast<const uint4*>(g_X2 + ((o*6 + i)*144)*40);
    const uint4* wi = reinterpret_cast<const uint4*>(g_W2 + ((o*6 + i)*25)*40);
    uint4 xa[8], wa[8];
#pragma unroll
    for (int j = 0; j < 8; ++j) {
        int q = lane + 32*j;                  // (tap k, quad): 25*10 = 250
        bool valid = (q < 250);
        int k = q / 10, quad = q - 10*k;
        int n = (r + k/5)*12 + (c + k%5);
        xa[j] = valid ? xi[n*10 + quad] : make_uint4(0,0,0,0);
        wa[j] = valid ? wi[k*10 + quad] : make_uint4(0,0,0,0);
    }
    int ham = 0;
#pragma unroll
    for (int j = 0; j < 8; ++j) ham += popc4(xa[j], wa[j]);
    ham = __reduce_add_sync(FULLMASK, ham);
    if (lane == 0) atomicAdd(&g_c2h[w], ham);
}

// ---------------- kernel 5: finisher ----------------
// Phase A: pool2 epilogue computed REDUNDANTLY per block from g_c2h (block-local
// min/max, deterministic & identical across blocks) -> no barrier before packX3.
// Then: packX3 -> gbar -> fc3 -> gbar -> packX4 -> gbar -> fc4 -> gbar -> packX5
// -> gbar -> fc5. Work strided by block so DRAM pulls spread over all 32 SMs.
__global__ void __launch_bounds__(FT, 1) k_finish(
    const float* __restrict__ b2,
    const float* __restrict__ rm_x3, const float* __restrict__ rm_x4,
    const float* __restrict__ rm_x5, float* __restrict__ out)
{
    __shared__ float shP[256];
    __shared__ float shmn[16], shmx[16];
    const int t = threadIdx.x;
    const int lane = t & 31;
    const int wid = t >> 5;               // 0..15
    const int b = blockIdx.x;             // 0..31

    // ---- Phase A: conv2 epilogue + pool2 + block-local min/max (redundant per block)
    float cellv = 0.0f;
    if (t < 256) {
        int o = t >> 4, rem = t & 15, pr = rem >> 2, pc = rem & 3;
        float bo = b2[o];
        float m = 0.0f;
#pragma unroll
        for (int win = 0; win < 4; ++win) {
            int r = 2*pr + (win >> 1), c = 2*pc + (win & 1);
            int ham = __ldcg(&g_c2h[o*64 + r*8 + c]);
            float cnt = (float)(192000 - ham);
            float q = __fmul_rn(cnt, (1.0f/192000.0f));
            float y = __fsub_rn(__fmul_rn(2.0f, q), 1.0f);
            float v = fmaxf(__fadd_rn(__fmul_rn(y, 150.0f), bo), 0.0f);
            m = fmaxf(m, v);
        }
        shP[t] = m;
        cellv = m;
    }
    // block-local deterministic min/max over the 256 cells
    float vmn = (t < 256) ? cellv : __int_as_float(0x7f800000);
    float vmx = (t < 256) ? cellv : 0.0f;
#pragma unroll
    for (int off = 16; off; off >>= 1) {
        vmn = fminf(vmn, __shfl_xor_sync(FULLMASK, vmn, off));
        vmx = fmaxf(vmx, __shfl_xor_sync(FULLMASK, vmx, off));
    }
    if (lane == 0) { shmn[wid] = vmn; shmx[wid] = vmx; }
    __syncthreads();
    float mn2 = shmn[0], mx2 = shmx[0];
#pragma unroll
    for (int i = 1; i < 16; ++i) { mn2 = fminf(mn2, shmn[i]); mx2 = fmaxf(mx2, shmx[i]); }
    float den2 = mx2 - mn2;

    // ---- Phase B: pack X3 — 256 rows: row = b*8 + wid (wid<8)
    if (wid < 8) {
        int row = b*8 + wid;
        float pv = __fdiv_rn(shP[row] - mn2, den2);
        pack_row(rm_x3 + (size_t)row * 1280, thr_of(pv), g_X3 + row*40, lane);
    }
    gbar(FB);

    // ---- Phase C: fc3 — 120 outputs, m = wid*32 + b (wid<4, guard m<120)
    if (wid < 4) {
        int m = wid*32 + b;
        if (m < 120) {
            int h = 0;
            for (int n = lane; n < 256; n += 32) {
                const uint4* xr = reinterpret_cast<const uint4*>(g_X3 + n*40);
                const uint4* sr = reinterpret_cast<const uint4*>(g_SW3 + (m*256 + n)*40);
#pragma unroll
                for (int q = 0; q < 10; ++q) h += popc4(xr[q], sr[q]);
            }
            h = __reduce_add_sync(FULLMASK, h);
            if (lane == 0) {
                float cnt = (float)(327680 - h + __ldcg(&g_pos3[m]));   // 256*1280 - H + pos
                float q = __fmul_rn(cnt, (1.0f/328960.0f));             // 257*1280
                float o3 = __fmul_rn(__fsub_rn(__fmul_rn(2.0f, q), 1.0f), 257.0f);
                float rv = fmaxf(o3, 0.0f);
                g_f1[m] = rv;
                atomicMin(&g_mm[4], __float_as_uint(rv));
                atomicMax(&g_mm[5], __float_as_uint(rv));
            }
        }
    }
    gbar(FB);

    // ---- Phase D: pack X4 — 120 rows, row = wid*32 + b (wid<4, guard)
    if (wid < 4) {
        int row = wid*32 + b;
        if (row < 120) {
            float mn = __uint_as_float(__ldcg(&g_mm[4]));
            float mx = __uint_as_float(__ldcg(&g_mm[5]));
            float den = mx - mn;
            float pv = __fdiv_rn(__ldcg(&g_f1[row]) - mn, den);
            pack_row(rm_x4 + (size_t)row * 1280, thr_of(pv), g_X4 + row*40, lane);
        }
    }
    gbar(FB);

    // ---- Phase E: fc4 — 84 outputs, m = wid*32 + b (wid<3, guard m<84)
    if (wid < 3) {
        int m = wid*32 + b;
        if (m < 84) {
            int h = 0;
            for (int n = lane; n < 120; n += 32) {
                const uint4* xr = reinterpret_cast<const uint4*>(g_X4 + n*40);
                const uint4* sr = reinterpret_cast<const uint4*>(g_SW4 + (m*120 + n)*40);
#pragma unroll
                for (int q = 0; q < 10; ++q) h += popc4(xr[q], sr[q]);
            }
            h = __reduce_add_sync(FULLMASK, h);
            if (lane == 0) {
                float cnt = (float)(153600 - h + __ldcg(&g_pos4[m]));   // 120*1280 - H + pos
                float q = __fmul_rn(cnt, (1.0f/154880.0f));             // 121*1280
                float o4 = __fmul_rn(__fsub_rn(__fmul_rn(2.0f, q), 1.0f), 121.0f);
                float rv = fmaxf(o4, 0.0f);
                g_f2[m] = rv;
                atomicMin(&g_mm[6], __float_as_uint(rv));
                atomicMax(&g_mm[7], __float_as_uint(rv));
            }
        }
    }
    gbar(FB);

    // ---- Phase F: pack X5 — 84 rows, row = wid*32 + b (wid<3, guard)
    if (wid < 3) {
        int row = wid*32 + b;
        if (row < 84) {
            float mn = __uint_as_float(__ldcg(&g_mm[6]));
            float mx = __uint_as_float(__ldcg(&g_mm[7]));
            float den = mx - mn;
            float pv = __fdiv_rn(__ldcg(&g_f2[row]) - mn, den);
            pack_row(rm_x5 + (size_t)row * 1280, thr_of(pv), g_X5 + row*40, lane);
        }
    }
    gbar(FB);

    // ---- Phase G: fc5 — 10 outputs, m = b (warp 0 of blocks 0..9)
    if (wid == 0 && b < 10) {
        int m = b;
        int h = 0;
        for (int n = lane; n < 84; n += 32) {
            const uint4* xr = reinterpret_cast<const uint4*>(g_X5 + n*40);
            const uint4* sr = reinterpret_cast<const uint4*>(g_SW5 + (m*84 + n)*40);
#pragma unroll
            for (int q = 0; q < 10; ++q) h += popc4(xr[q], sr[q]);
        }
        h = __reduce_add_sync(FULLMASK, h);
        if (lane == 0) {
            float cnt = (float)(107520 - h + __ldcg(&g_pos5[m]));   // 84*1280 - H + pos
            float q = __fmul_rn(cnt, (1.0f/108800.0f));             // 85*1280
            out[m] = __fmul_rn(__fsub_rn(__fmul_rn(2.0f, q), 1.0f), 85.0f);
        }
    }
}

// ---------------- launch ----------------
extern "C" void kernel_launch(void* const* d_in, const int* in_sizes, int n_in,
                              void* d_out, int out_size) {
    const float* img    = (const float*)d_in[0];
    const float* w1     = (const float*)d_in[1];
    const float* b1     = (const float*)d_in[2];
    const float* w2     = (const float*)d_in[3];
    const float* b2     = (const float*)d_in[4];
    const float* wfc3   = (const float*)d_in[5];
    const float* bfc3   = (const float*)d_in[6];
    const float* wfc4   = (const float*)d_in[7];
    const float* bfc4   = (const float*)d_in[8];
    const float* wfc5   = (const float*)d_in[9];
    const float* bfc5   = (const float*)d_in[10];
    const float* rm_in1 = (const float*)d_in[11];
    const float* rm_k1  = (const float*)d_in[12];
    const float* rm_in2 = (const float*)d_in[13];
    const float* rm_k2  = (const float*)d_in[14];
    const float* rm_x3  = (const float*)d_in[15];
    const float* rm_w3  = (const float*)d_in[16];
    const float* rm_b3  = (const float*)d_in[17];
    const float* rm_x4  = (const float*)d_in[18];
    const float* rm_w4  = (const float*)d_in[19];
    const float* rm_b4  = (const float*)d_in[20];
    const float* rm_x5  = (const float*)d_in[21];
    const float* rm_w5  = (const float*)d_in[22];
    const float* rm_b5  = (const float*)d_in[23];
    float* out = (float*)d_out;

    k_pack_static_all<<<2048, 256>>>(img, w1, w2, wfc3, wfc4, wfc5, bfc3, bfc4, bfc5,
                                     rm_in1, rm_k1, rm_k2, rm_w3, rm_w4, rm_w5,
                                     rm_b3, rm_b4, rm_b5);
    k_conv1pool1<<<108, 256>>>(b1);
    k_pack_X2<<<1728, 256>>>(rm_in2);
    k_conv2part<<<768, 256>>>();
    k_finish<<<FB, FT>>>(b2, rm_x3, rm_x4, rm_x5, out);
}

// round 15
// speedup vs baseline: 1.3171x; 1.0105x over previous
#include <cuda_runtime.h>

#define FULLMASK 0xffffffffu
#define FB 32       // finisher blocks
#define FT 512      // finisher threads

// ---------------- scratch (__device__ globals; no allocation allowed) ----------------
__device__ __align__(16) unsigned g_X1[6*784*40];      // packed bip(image, rm_in1)
__device__ __align__(16) unsigned g_W1[6*25*40];       // packed bip(w1, rm_k1)
__device__ __align__(16) unsigned g_W2[16*6*25*40];    // packed bip(w2, rm_k2)
__device__ __align__(16) unsigned g_X2[16*6*144*40];   // packed bip(p1norm, rm_in2)
__device__ __align__(16) unsigned g_SW3[120*256*40];   // [m][n][40]
__device__ __align__(16) unsigned g_SW4[84*120*40];    // [m][n][40]
__device__ __align__(16) unsigned g_SW5[10*84*40];     // [m][n][40]
__device__ __align__(16) unsigned g_X3[256*40];
__device__ __align__(16) unsigned g_X4[120*40];
__device__ __align__(16) unsigned g_X5[84*40];
__device__ int g_pos3[120];
__device__ int g_pos4[84];
__device__ int g_pos5[10];
__device__ int g_c2h[1024];       // conv2 partial hamming sums (window-major o*64+r*8+c)
__device__ float g_P1[864];       // pool1 (6,12,12) un-normalized
__device__ float g_f1[120];       // relu(fc3) un-normalized
__device__ float g_f2[84];        // relu(fc4) un-normalized
__device__ unsigned g_mm[8];      // bit-punned nonneg float min/max pairs ([0,1]=pool1 [4,5]=fc3 [6,7]=fc4)
__device__ unsigned g_arrive;     // barrier arrival counter (self-resetting)
__device__ unsigned g_gen2;       // barrier generation (monotonic across replays)

// ---------------- helpers ----------------

__device__ __forceinline__ int popc4(uint4 a, uint4 b) {
    return __popc(a.x ^ b.x) + __popc(a.y ^ b.y) + __popc(a.z ^ b.z) + __popc(a.w ^ b.w);
}

// Pack one bitstream row: 1280 floats -> 40 uint32 words. All 40 scalar loads
// hoisted before the ballot chain for max MLP. Natural bit layout everywhere.
__device__ __forceinline__ void pack_row(const float* __restrict__ src, float thr,
                                         unsigned* __restrict__ dst, int lane) {
    float v[40];
#pragma unroll
    for (int wd = 0; wd < 40; ++wd) v[wd] = src[wd*32 + lane];
#pragma unroll
    for (int wd = 0; wd < 40; wd += 4) {
        unsigned b0 = __ballot_sync(FULLMASK, thr > v[wd+0]);
        unsigned b1 = __ballot_sync(FULLMASK, thr > v[wd+1]);
        unsigned b2 = __ballot_sync(FULLMASK, thr > v[wd+2]);
        unsigned b3 = __ballot_sync(FULLMASK, thr > v[wd+3]);
        if (lane == 0) *reinterpret_cast<uint4*>(dst + wd) = make_uint4(b0, b1, b2, b3);
    }
}

__device__ __forceinline__ int pack_row_popc(const float* __restrict__ src, float thr, int lane) {
    float v[40];
#pragma unroll
    for (int wd = 0; wd < 40; ++wd) v[wd] = src[wd*32 + lane];
    int s = 0;
#pragma unroll
    for (int wd = 0; wd < 40; ++wd) s += __popc(__ballot_sync(FULLMASK, thr > v[wd]));
    return s;
}

__device__ __forceinline__ float thr_of(float v) {
    return __fmul_rn(__fadd_rn(v, 1.0f), 0.5f);
}

// Counter+gen grid barrier among `nblocks` co-resident blocks. gen grows
// monotonically across barriers AND graph replays; counter self-resets.
__device__ __forceinline__ void gbar(int nblocks) {
    __syncthreads();
    if (threadIdx.x == 0) {
        __threadfence();
        unsigned gen = *(volatile unsigned*)&g_gen2;
        if (atomicAdd(&g_arrive, 1u) == (unsigned)(nblocks - 1)) {
            atomicExch(&g_arrive, 0u);
            __threadfence();
            atomicAdd(&g_gen2, 1u);
        } else {
            while (*(volatile unsigned*)&g_gen2 == gen) __nanosleep(64);
        }
        __threadfence();
    }
    __syncthreads();
}

// ---------------- kernel 1: pack X1 + W1 (24.6MB) + init ----------------
__global__ void k_pack_x1w1(const float* __restrict__ img, const float* __restrict__ w1,
                            const float* __restrict__ rm_in1, const float* __restrict__ rm_k1) {
    if (blockIdx.x == 0 && threadIdx.x < 8)
        g_mm[threadIdx.x] = (threadIdx.x & 1) ? 0u : 0x7f800000u;  // min=+inf, max=0
    if (blockIdx.x == 1 && threadIdx.x < 256) {                    // zero conv2 partials (replay-safe)
        g_c2h[threadIdx.x] = 0;
        g_c2h[threadIdx.x + 256] = 0;
        g_c2h[threadIdx.x + 512] = 0;
        g_c2h[threadIdx.x + 768] = 0;
    }
    int lane = threadIdx.x & 31;
    int gw = (blockIdx.x * blockDim.x + threadIdx.x) >> 5;   // 607*8 = 4856 warps
    const int RX1 = 6*784;           // 4704
    const int RW1 = RX1 + 6*25;      // 4854
    if (gw < RX1) {
        pack_row(rm_in1 + (size_t)gw * 1280, thr_of(img[gw % 784]), g_X1 + gw*40, lane);
    } else if (gw < RW1) {
        int r = gw - RX1;
        pack_row(rm_k1 + (size_t)r * 1280, thr_of(w1[r]), g_W1 + r*40, lane);
    }
}

// ---------------- kernel 2: role-split — conv1pool1 (blocks 0..107) || pack W2+SW+biases ----------------
__global__ void k_conv1_and_pack(const float* __restrict__ b1, const float* __restrict__ w2,
                                 const float* __restrict__ wfc3, const float* __restrict__ wfc4,
                                 const float* __restrict__ wfc5,
                                 const float* __restrict__ bfc3, const float* __restrict__ bfc4,
                                 const float* __restrict__ bfc5,
                                 const float* __restrict__ rm_k2,
                                 const float* __restrict__ rm_w3, const float* __restrict__ rm_w4,
                                 const float* __restrict__ rm_w5,
                                 const float* __restrict__ rm_b3, const float* __restrict__ rm_b4,
                                 const float* __restrict__ rm_b5) {
    int lane = threadIdx.x & 31;
    int wid = threadIdx.x >> 5;

    if (blockIdx.x < 108) {
        // ---- conv1 + pool1: warp = pool cell (4 windows); 108*8 = 864 warps
        int gw = blockIdx.x * 8 + wid;
        int o = gw / 144, rem = gw % 144, pr = rem / 12, pc = rem % 12;
        const uint4* xb = reinterpret_cast<const uint4*>(g_X1 + o*784*40);
        const uint4* wb = reinterpret_cast<const uint4*>(g_W1 + o*25*40);
        float bo = b1[o];
        float m = 0.0f;
#pragma unroll
        for (int win = 0; win < 4; ++win) {
            int r = 2*pr + (win >> 1), c = 2*pc + (win & 1);
            int ham = 0;
            for (int q = lane; q < 250; q += 32) {        // (tap k, quad): 25*10
                int k = q / 10, quad = q - 10*k;
                int n = (r + k/5)*28 + (c + k%5);
                ham += popc4(xb[n*10 + quad], wb[k*10 + quad]);
            }
            ham = __reduce_add_sync(FULLMASK, ham);
            float cnt = (float)(32000 - ham);
            float q2 = __fmul_rn(cnt, (1.0f/32000.0f));
            float y = __fsub_rn(__fmul_rn(2.0f, q2), 1.0f);
            float v = fmaxf(__fadd_rn(__fmul_rn(y, 25.0f), bo), 0.0f);
            m = fmaxf(m, v);
        }
        if (lane == 0) {
            g_P1[gw] = m;
            atomicMin(&g_mm[0], __float_as_uint(m));
            atomicMax(&g_mm[1], __float_as_uint(m));
        }
        return;
    }

    // ---- pack W2 + SW3/4/5 + bias popcounts (216.5MB)
    int pw = (blockIdx.x - 108) * 8 + wid;               // pack-warp id
    int npw = (gridDim.x - 108) * 8;
    const int RW2 = 16*6*25;             // 2400
    const int RS3 = RW2 + 256*120;       // 33120
    const int RS4 = RS3 + 120*84;        // 43200
    const int RS5 = RS4 + 84*10;         // 44040
    const int RB3 = RS5 + 120;
    const int RB4 = RB3 + 84;
    const int RB5 = RB4 + 10;            // 44254
    for (int row = pw; row < RB5; row += npw) {
        if (row < RW2) {
            pack_row(rm_k2 + (size_t)row * 1280, thr_of(w2[row]), g_W2 + row*40, lane);
        } else if (row < RS3) {
            int r = row - RW2; int n = r / 120, m = r % 120;   // rm_w3 is [n][m][l]
            pack_row(rm_w3 + (size_t)r * 1280, thr_of(wfc3[r]), g_SW3 + (m*256 + n)*40, lane);
        } else if (row < RS4) {
            int r = row - RS3; int n = r / 84, m = r % 84;
            pack_row(rm_w4 + (size_t)r * 1280, thr_of(wfc4[r]), g_SW4 + (m*120 + n)*40, lane);
        } else if (row < RS5) {
            int r = row - RS4; int n = r / 10, m = r % 10;
            pack_row(rm_w5 + (size_t)r * 1280, thr_of(wfc5[r]), g_SW5 + (m*84 + n)*40, lane);
        } else if (row < RB3) {
            int r = row - RS5;
            int s = pack_row_popc(rm_b3 + (size_t)r * 1280, thr_of(bfc3[r]), lane);
            if (lane == 0) g_pos3[r] = s;
        } else if (row < RB4) {
            int r = row - RB3;
            int s = pack_row_popc(rm_b4 + (size_t)r * 1280, thr_of(bfc4[r]), lane);
            if (lane == 0) g_pos4[r] = s;
        } else {
            int r = row - RB4;
            int s = pack_row_popc(rm_b5 + (size_t)r * 1280, thr_of(bfc5[r]), lane);
            if (lane == 0) g_pos5[r] = s;
        }
    }
}

// ---------------- kernel 3: pack X2 (71MB rm_in2) ----------------
__global__ void k_pack_X2(const float* __restrict__ rm_in2) {  // <<<1728,256>>> = 13824 warps
    int lane = threadIdx.x & 31;
    int row = (blockIdx.x * blockDim.x + threadIdx.x) >> 5;    // 0..13823
    float mn = __uint_as_float(g_mm[0]);
    float mx = __uint_as_float(g_mm[1]);
    float den = mx - mn;
    float p = g_P1[row % 864];                                 // row=(o*6+i)*144+n; %864 = i*144+n
    float pv = __fdiv_rn(p - mn, den);                         // norm01 (runtime denom: true div)
    pack_row(rm_in2 + (size_t)row * 1280, thr_of(pv), g_X2 + row*40, lane);
}

// ---------------- kernel 4: finisher (conv2 -> pool2 -> packX3 -> fc3 -> ... -> fc5) ----------------
__global__ void __launch_bounds__(FT, 1) k_finish(
    const float* __restrict__ b2,
    const float* __restrict__ rm_x3, const float* __restrict__ rm_x4,
    const float* __restrict__ rm_x5, float* __restrict__ out)
{
    __shared__ float shP[256];
    __shared__ float shmn[16], shmx[16];
    const int t = threadIdx.x;
    const int lane = t & 31;
    const int wid = t >> 5;               // 0..15
    const int b = blockIdx.x;             // 0..31
    const int gw = b * 16 + wid;          // 0..511

    // ---- Phase 0: conv2 partial hammings — 6144 (window,channel) warp-tasks, 12 per warp.
    //      All 16 loads per task hoisted (predicated) -> L2 latency hiding.
#pragma unroll
    for (int j = 0; j < 12; ++j) {
        int task = gw + 512*j;                // 0..6143
        int w = task / 6;                     // window 0..1023
        int i = task - 6*w;                   // channel 0..5
        int o = w >> 6, rc = w & 63, r = rc >> 3, c = rc & 7;
        const uint4* xi = reinterpret_cast<const uint4*>(g_X2 + ((o*6 + i)*144)*40);
        const uint4* wi = reinterpret_cast<const uint4*>(g_W2 + ((o*6 + i)*25)*40);
        uint4 xa[8], wa[8];
#pragma unroll
        for (int u = 0; u < 8; ++u) {
            int q = lane + 32*u;              // (tap k, quad): 25*10 = 250
            bool valid = (q < 250);
            int k = q / 10, quad = q - 10*k;
            int n = (r + k/5)*12 + (c + k%5);
            xa[u] = valid ? xi[n*10 + quad] : make_uint4(0,0,0,0);
            wa[u] = valid ? wi[k*10 + quad] : make_uint4(0,0,0,0);
        }
        int ham = 0;
#pragma unroll
        for (int u = 0; u < 8; ++u) ham += popc4(xa[u], wa[u]);
        ham = __reduce_add_sync(FULLMASK, ham);
        if (lane == 0) atomicAdd(&g_c2h[w], ham);
    }
    gbar(FB);

    // ---- Phase A: conv2 epilogue + pool2 + block-local min/max (redundant per block)
    float cellv = 0.0f;
    if (t < 256) {
        int o = t >> 4, rem = t & 15, pr = rem >> 2, pc = rem & 3;
        float bo = b2[o];
        float m = 0.0f;
#pragma unroll
        for (int win = 0; win < 4; ++win) {
            int r = 2*pr + (win >> 1), c = 2*pc + (win & 1);
            int ham = __ldcg(&g_c2h[o*64 + r*8 + c]);
            float cnt = (float)(192000 - ham);
            float q = __fmul_rn(cnt, (1.0f/192000.0f));
            float y = __fsub_rn(__fmul_rn(2.0f, q), 1.0f);
            float v = fmaxf(__fadd_rn(__fmul_rn(y, 150.0f), bo), 0.0f);
            m = fmaxf(m, v);
        }
        shP[t] = m;
        cellv = m;
    }
    float vmn = (t < 256) ? cellv : __int_as_float(0x7f800000);
    float vmx = (t < 256) ? cellv : 0.0f;
#pragma unroll
    for (int off = 16; off; off >>= 1) {
        vmn = fminf(vmn, __shfl_xor_sync(FULLMASK, vmn, off));
        vmx = fmaxf(vmx, __shfl_xor_sync(FULLMASK, vmx, off));
    }
    if (lane == 0) { shmn[wid] = vmn; shmx[wid] = vmx; }
    __syncthreads();
    float mn2 = shmn[0], mx2 = shmx[0];
#pragma unroll
    for (int i = 1; i < 16; ++i) { mn2 = fminf(mn2, shmn[i]); mx2 = fmaxf(mx2, shmx[i]); }
    float den2 = mx2 - mn2;

    // ---- Phase B: pack X3 — 256 rows: row = b*8 + wid (wid<8)
    if (wid < 8) {
        int row = b*8 + wid;
        float pv = __fdiv_rn(shP[row] - mn2, den2);
        pack_row(rm_x3 + (size_t)row * 1280, thr_of(pv), g_X3 + row*40, lane);
    }
    gbar(FB);

    // ---- Phase C: fc3 — 120 outputs, m = wid*32 + b (wid<4, guard m<120)
    if (wid < 4) {
        int m = wid*32 + b;
        if (m < 120) {
            int h = 0;
            for (int n = lane; n < 256; n += 32) {
                const uint4* xr = reinterpret_cast<const uint4*>(g_X3 + n*40);
                const uint4* sr = reinterpret_cast<const uint4*>(g_SW3 + (m*256 + n)*40);
#pragma unroll
                for (int q = 0; q < 10; ++q) h += popc4(xr[q], sr[q]);
            }
            h = __reduce_add_sync(FULLMASK, h);
            if (lane == 0) {
                float cnt = (float)(327680 - h + __ldcg(&g_pos3[m]));   // 256*1280 - H + pos
                float q = __fmul_rn(cnt, (1.0f/328960.0f));             // 257*1280
                float o3 = __fmul_rn(__fsub_rn(__fmul_rn(2.0f, q), 1.0f), 257.0f);
                float rv = fmaxf(o3, 0.0f);
                g_f1[m] = rv;
                atomicMin(&g_mm[4], __float_as_uint(rv));
                atomicMax(&g_mm[5], __float_as_uint(rv));
            }
        }
    }
    gbar(FB);

    // ---- Phase D: pack X4 — 120 rows, row = wid*32 + b (wid<4, guard)
    if (wid < 4) {
        int row = wid*32 + b;
        if (row < 120) {
            float mn = __uint_as_float(__ldcg(&g_mm[4]));
            float mx = __uint_as_float(__ldcg(&g_mm[5]));
            float den = mx - mn;
            float pv = __fdiv_rn(__ldcg(&g_f1[row]) - mn, den);
            pack_row(rm_x4 + (size_t)row * 1280, thr_of(pv), g_X4 + row*40, lane);
        }
    }
    gbar(FB);

    // ---- Phase E: fc4 — 84 outputs, m = wid*32 + b (wid<3, guard m<84)
    if (wid < 3) {
        int m = wid*32 + b;
        if (m < 84) {
            int h = 0;
            for (int n = lane; n < 120; n += 32) {
                const uint4* xr = reinterpret_cast<const uint4*>(g_X4 + n*40);
                const uint4* sr = reinterpret_cast<const uint4*>(g_SW4 + (m*120 + n)*40);
#pragma unroll
                for (int q = 0; q < 10; ++q) h += popc4(xr[q], sr[q]);
            }
            h = __reduce_add_sync(FULLMASK, h);
            if (lane == 0) {
                float cnt = (float)(153600 - h + __ldcg(&g_pos4[m]));   // 120*1280 - H + pos
                float q = __fmul_rn(cnt, (1.0f/154880.0f));             // 121*1280
                float o4 = __fmul_rn(__fsub_rn(__fmul_rn(2.0f, q), 1.0f), 121.0f);
                float rv = fmaxf(o4, 0.0f);
                g_f2[m] = rv;
                atomicMin(&g_mm[6], __float_as_uint(rv));
                atomicMax(&g_mm[7], __float_as_uint(rv));
            }
        }
    }
    gbar(FB);

    // ---- Phase F: pack X5 — 84 rows, row = wid*32 + b (wid<3, guard)
    if (wid < 3) {
        int row = wid*32 + b;
        if (row < 84) {
            float mn = __uint_as_float(__ldcg(&g_mm[6]));
            float mx = __uint_as_float(__ldcg(&g_mm[7]));
            float den = mx - mn;
            float pv = __fdiv_rn(__ldcg(&g_f2[row]) - mn, den);
            pack_row(rm_x5 + (size_t)row * 1280, thr_of(pv), g_X5 + row*40, lane);
        }
    }
    gbar(FB);

    // ---- Phase G: fc5 — 10 outputs, m = b (warp 0 of blocks 0..9)
    if (wid == 0 && b < 10) {
        int m = b;
        int h = 0;
        for (int n = lane; n < 84; n += 32) {
            const uint4* xr = reinterpret_cast<const uint4*>(g_X5 + n*40);
            const uint4* sr = reinterpret_cast<const uint4*>(g_SW5 + (m*84 + n)*40);
#pragma unroll
            for (int q = 0; q < 10; ++q) h += popc4(xr[q], sr[q]);
        }
        h = __reduce_add_sync(FULLMASK, h);
        if (lane == 0) {
            float cnt = (float)(107520 - h + __ldcg(&g_pos5[m]));   // 84*1280 - H + pos
            float q = __fmul_rn(cnt, (1.0f/108800.0f));             // 85*1280
            out[m] = __fmul_rn(__fsub_rn(__fmul_rn(2.0f, q), 1.0f), 85.0f);
        }
    }
}

// ---------------- launch ----------------
extern "C" void kernel_launch(void* const* d_in, const int* in_sizes, int n_in,
                              void* d_out, int out_size) {
    const float* img    = (const float*)d_in[0];
    const float* w1     = (const float*)d_in[1];
    const float* b1     = (const float*)d_in[2];
    const float* w2     = (const float*)d_in[3];
    const float* b2     = (const float*)d_in[4];
    const float* wfc3   = (const float*)d_in[5];
    const float* bfc3   = (const float*)d_in[6];
    const float* wfc4   = (const float*)d_in[7];
    const float* bfc4   = (const float*)d_in[8];
    const float* wfc5   = (const float*)d_in[9];
    const float* bfc5   = (const float*)d_in[10];
    const float* rm_in1 = (const float*)d_in[11];
    const float* rm_k1  = (const float*)d_in[12];
    const float* rm_in2 = (const float*)d_in[13];
    const float* rm_k2  = (const float*)d_in[14];
    const float* rm_x3  = (const float*)d_in[15];
    const float* rm_w3  = (const float*)d_in[16];
    const float* rm_b3  = (const float*)d_in[17];
    const float* rm_x4  = (const float*)d_in[18];
    const float* rm_w4  = (const float*)d_in[19];
    const float* rm_b4  = (const float*)d_in[20];
    const float* rm_x5  = (const float*)d_in[21];
    const float* rm_w5  = (const float*)d_in[22];
    const float* rm_b5  = (const float*)d_in[23];
    float* out = (float*)d_out;

    k_pack_x1w1<<<607, 256>>>(img, w1, rm_in1, rm_k1);
    k_conv1_and_pack<<<2048, 256>>>(b1, w2, wfc3, wfc4, wfc5, bfc3, bfc4, bfc5,
                                    rm_k2, rm_w3, rm_w4, rm_w5, rm_b3, rm_b4, rm_b5);
    k_pack_X2<<<1728, 256>>>(rm_in2);
    k_finish<<<FB, FT>>>(b2, rm_x3, rm_x4, rm_x5, out);
}

// round 16
// speedup vs baseline: 1.4258x; 1.0826x over previous
#include <cuda_runtime.h>

#define FULLMASK 0xffffffffu
#define FB 32       // finisher blocks
#define FT 512      // finisher threads

// ---------------- scratch (__device__ globals; no allocation allowed) ----------------
__device__ __align__(16) unsigned g_X1[6*784*40];      // packed bip(image, rm_in1)
__device__ __align__(16) unsigned g_W1[6*25*40];       // packed bip(w1, rm_k1)
__device__ __align__(16) unsigned g_W2[16*6*25*40];    // packed bip(w2, rm_k2)
__device__ __align__(16) unsigned g_X2[16*6*144*40];   // packed bip(p1norm, rm_in2)
__device__ __align__(16) unsigned g_SW3[120*256*40];   // [m][n][40]
__device__ __align__(16) unsigned g_SW4[84*120*40];    // [m][n][40]
__device__ __align__(16) unsigned g_SW5[10*84*40];     // [m][n][40]
__device__ __align__(16) unsigned g_X3[256*40];
__device__ __align__(16) unsigned g_X4[120*40];
__device__ __align__(16) unsigned g_X5[84*40];
__device__ int g_pos3[120];
__device__ int g_pos4[84];
__device__ int g_pos5[10];
__device__ int g_c2h[1024];       // conv2 partial hamming sums (window-major o*64+r*8+c)
__device__ float g_P1[864];       // pool1 (6,12,12) un-normalized
__device__ float g_f1[120];       // relu(fc3) un-normalized
__device__ float g_f2[84];        // relu(fc4) un-normalized
__device__ unsigned g_mm[8];      // bit-punned nonneg float min/max pairs ([0,1]=pool1 [4,5]=fc3 [6,7]=fc4)
__device__ unsigned g_arrive;     // barrier arrival counter (self-resetting)
__device__ unsigned g_gen2;       // barrier generation (monotonic across replays)

// ---------------- helpers ----------------

__device__ __forceinline__ int popc4(uint4 a, uint4 b) {
    return __popc(a.x ^ b.x) + __popc(a.y ^ b.y) + __popc(a.z ^ b.z) + __popc(a.w ^ b.w);
}

// Pack one bitstream row: 1280 floats -> 40 uint32 words. All 40 scalar loads
// hoisted before the ballot chain for max MLP. Natural bit layout everywhere.
__device__ __forceinline__ void pack_row(const float* __restrict__ src, float thr,
                                         unsigned* __restrict__ dst, int lane) {
    float v[40];
#pragma unroll
    for (int wd = 0; wd < 40; ++wd) v[wd] = src[wd*32 + lane];
#pragma unroll
    for (int wd = 0; wd < 40; wd += 4) {
        unsigned b0 = __ballot_sync(FULLMASK, thr > v[wd+0]);
        unsigned b1 = __ballot_sync(FULLMASK, thr > v[wd+1]);
        unsigned b2 = __ballot_sync(FULLMASK, thr > v[wd+2]);
        unsigned b3 = __ballot_sync(FULLMASK, thr > v[wd+3]);
        if (lane == 0) *reinterpret_cast<uint4*>(dst + wd) = make_uint4(b0, b1, b2, b3);
    }
}

__device__ __forceinline__ int pack_row_popc(const float* __restrict__ src, float thr, int lane) {
    float v[40];
#pragma unroll
    for (int wd = 0; wd < 40; ++wd) v[wd] = src[wd*32 + lane];
    int s = 0;
#pragma unroll
    for (int wd = 0; wd < 40; ++wd) s += __popc(__ballot_sync(FULLMASK, thr > v[wd]));
    return s;
}

__device__ __forceinline__ float thr_of(float v) {
    return __fmul_rn(__fadd_rn(v, 1.0f), 0.5f);
}

// Counter+gen grid barrier among `nblocks` co-resident blocks. gen grows
// monotonically across barriers AND graph replays; counter self-resets.
__device__ __forceinline__ void gbar(int nblocks) {
    __syncthreads();
    if (threadIdx.x == 0) {
        __threadfence();
        unsigned gen = *(volatile unsigned*)&g_gen2;
        if (atomicAdd(&g_arrive, 1u) == (unsigned)(nblocks - 1)) {
            atomicExch(&g_arrive, 0u);
            __threadfence();
            atomicAdd(&g_gen2, 1u);
        } else {
            while (*(volatile unsigned*)&g_gen2 == gen) __nanosleep(64);
        }
        __threadfence();
    }
    __syncthreads();
}

// ---------------- kernel 1: pack X1 + W1 (24.6MB) + init ----------------
__global__ void k_pack_x1w1(const float* __restrict__ img, const float* __restrict__ w1,
                            const float* __restrict__ rm_in1, const float* __restrict__ rm_k1) {
    if (blockIdx.x == 0 && threadIdx.x < 8)
        g_mm[threadIdx.x] = (threadIdx.x & 1) ? 0u : 0x7f800000u;  // min=+inf, max=0
    if (blockIdx.x == 1 && threadIdx.x < 256) {                    // zero conv2 partials (replay-safe)
        g_c2h[threadIdx.x] = 0;
        g_c2h[threadIdx.x + 256] = 0;
        g_c2h[threadIdx.x + 512] = 0;
        g_c2h[threadIdx.x + 768] = 0;
    }
    int lane = threadIdx.x & 31;
    int gw = (blockIdx.x * blockDim.x + threadIdx.x) >> 5;   // 607*8 = 4856 warps
    const int RX1 = 6*784;           // 4704
    const int RW1 = RX1 + 6*25;      // 4854
    if (gw < RX1) {
        pack_row(rm_in1 + (size_t)gw * 1280, thr_of(img[gw % 784]), g_X1 + gw*40, lane);
    } else if (gw < RW1) {
        int r = gw - RX1;
        pack_row(rm_k1 + (size_t)r * 1280, thr_of(w1[r]), g_W1 + r*40, lane);
    }
}

// ---------------- kernel 2: role-split — conv1pool1 (blocks 0..107) || pack W2+SW+biases ----------------
__global__ void k_conv1_and_pack(const float* __restrict__ b1, const float* __restrict__ w2,
                                 const float* __restrict__ wfc3, const float* __restrict__ wfc4,
                                 const float* __restrict__ wfc5,
                                 const float* __restrict__ bfc3, const float* __restrict__ bfc4,
                                 const float* __restrict__ bfc5,
                                 const float* __restrict__ rm_k2,
                                 const float* __restrict__ rm_w3, const float* __restrict__ rm_w4,
                                 const float* __restrict__ rm_w5,
                                 const float* __restrict__ rm_b3, const float* __restrict__ rm_b4,
                                 const float* __restrict__ rm_b5) {
    int lane = threadIdx.x & 31;
    int wid = threadIdx.x >> 5;

    if (blockIdx.x < 108) {
        // ---- conv1 + pool1: warp = pool cell (4 windows); 108*8 = 864 warps
        int gw = blockIdx.x * 8 + wid;
        int o = gw / 144, rem = gw % 144, pr = rem / 12, pc = rem % 12;
        const uint4* xb = reinterpret_cast<const uint4*>(g_X1 + o*784*40);
        const uint4* wb = reinterpret_cast<const uint4*>(g_W1 + o*25*40);
        float bo = b1[o];
        float m = 0.0f;
#pragma unroll
        for (int win = 0; win < 4; ++win) {
            int r = 2*pr + (win >> 1), c = 2*pc + (win & 1);
            int ham = 0;
            for (int q = lane; q < 250; q += 32) {        // (tap k, quad): 25*10
                int k = q / 10, quad = q - 10*k;
                int n = (r + k/5)*28 + (c + k%5);
                ham += popc4(xb[n*10 + quad], wb[k*10 + quad]);
            }
            ham = __reduce_add_sync(FULLMASK, ham);
            float cnt = (float)(32000 - ham);
            float q2 = __fmul_rn(cnt, (1.0f/32000.0f));
            float y = __fsub_rn(__fmul_rn(2.0f, q2), 1.0f);
            float v = fmaxf(__fadd_rn(__fmul_rn(y, 25.0f), bo), 0.0f);
            m = fmaxf(m, v);
        }
        if (lane == 0) {
            g_P1[gw] = m;
            atomicMin(&g_mm[0], __float_as_uint(m));
            atomicMax(&g_mm[1], __float_as_uint(m));
        }
        return;
    }

    // ---- pack W2 + SW3/4/5 + bias popcounts (216.5MB)
    int pw = (blockIdx.x - 108) * 8 + wid;               // pack-warp id
    int npw = (gridDim.x - 108) * 8;
    const int RW2 = 16*6*25;             // 2400
    const int RS3 = RW2 + 256*120;       // 33120
    const int RS4 = RS3 + 120*84;        // 43200
    const int RS5 = RS4 + 84*10;         // 44040
    const int RB3 = RS5 + 120;
    const int RB4 = RB3 + 84;
    const int RB5 = RB4 + 10;            // 44254
    for (int row = pw; row < RB5; row += npw) {
        if (row < RW2) {
            pack_row(rm_k2 + (size_t)row * 1280, thr_of(w2[row]), g_W2 + row*40, lane);
        } else if (row < RS3) {
            int r = row - RW2; int n = r / 120, m = r % 120;   // rm_w3 is [n][m][l]
            pack_row(rm_w3 + (size_t)r * 1280, thr_of(wfc3[r]), g_SW3 + (m*256 + n)*40, lane);
        } else if (row < RS4) {
            int r = row - RS3; int n = r / 84, m = r % 84;
            pack_row(rm_w4 + (size_t)r * 1280, thr_of(wfc4[r]), g_SW4 + (m*120 + n)*40, lane);
        } else if (row < RS5) {
            int r = row - RS4; int n = r / 10, m = r % 10;
            pack_row(rm_w5 + (size_t)r * 1280, thr_of(wfc5[r]), g_SW5 + (m*84 + n)*40, lane);
        } else if (row < RB3) {
            int r = row - RS5;
            int s = pack_row_popc(rm_b3 + (size_t)r * 1280, thr_of(bfc3[r]), lane);
            if (lane == 0) g_pos3[r] = s;
        } else if (row < RB4) {
            int r = row - RB3;
            int s = pack_row_popc(rm_b4 + (size_t)r * 1280, thr_of(bfc4[r]), lane);
            if (lane == 0) g_pos4[r] = s;
        } else {
            int r = row - RB4;
            int s = pack_row_popc(rm_b5 + (size_t)r * 1280, thr_of(bfc5[r]), lane);
            if (lane == 0) g_pos5[r] = s;
        }
    }
}

// ---------------- kernel 3: pack X2 (71MB rm_in2) ----------------
__global__ void k_pack_X2(const float* __restrict__ rm_in2) {  // <<<1728,256>>> = 13824 warps
    int lane = threadIdx.x & 31;
    int row = (blockIdx.x * blockDim.x + threadIdx.x) >> 5;    // 0..13823
    float mn = __uint_as_float(g_mm[0]);
    float mx = __uint_as_float(g_mm[1]);
    float den = mx - mn;
    float p = g_P1[row % 864];                                 // row=(o*6+i)*144+n; %864 = i*144+n
    float pv = __fdiv_rn(p - mn, den);                         // norm01 (runtime denom: true div)
    pack_row(rm_in2 + (size_t)row * 1280, thr_of(pv), g_X2 + row*40, lane);
}

// ---------------- kernel 4: conv2 partial hammings. warp = (window, channel). ----------------
// 1024 windows x 6 channels = 6144 warp-tasks over 768 blocks x 8 warps (all SMs).
// All 16 loads per warp hoisted (predicated) -> full L2 latency hiding.
__global__ void k_conv2part() {   // <<<768,256>>>
    int lane = threadIdx.x & 31;
    int wid = threadIdx.x >> 5;
    int task = blockIdx.x * 8 + wid;          // 0..6143
    int w = task / 6;                         // window 0..1023
    int i = task - 6*w;                       // channel 0..5
    int o = w >> 6, rc = w & 63, r = rc >> 3, c = rc & 7;
    const uint4* xi = reinterpret_cast<const uint4*>(g_X2 + ((o*6 + i)*144)*40);
    const uint4* wi = reinterpret_cast<const uint4*>(g_W2 + ((o*6 + i)*25)*40);
    uint4 xa[8], wa[8];
#pragma unroll
    for (int j = 0; j < 8; ++j) {
        int q = lane + 32*j;                  // (tap k, quad): 25*10 = 250
        bool valid = (q < 250);
        int k = q / 10, quad = q - 10*k;
        int n = (r + k/5)*12 + (c + k%5);
        xa[j] = valid ? xi[n*10 + quad] : make_uint4(0,0,0,0);
        wa[j] = valid ? wi[k*10 + quad] : make_uint4(0,0,0,0);
    }
    int ham = 0;
#pragma unroll
    for (int j = 0; j < 8; ++j) ham += popc4(xa[j], wa[j]);
    ham = __reduce_add_sync(FULLMASK, ham);
    if (lane == 0) atomicAdd(&g_c2h[w], ham);
}

// ---------------- kernel 5: finisher (pool2 epilogue -> packX3 -> fc3 -> ... -> fc5) ----------------
__global__ void __launch_bounds__(FT, 1) k_finish(
    const float* __restrict__ b2,
    const float* __restrict__ rm_x3, const float* __restrict__ rm_x4,
    const float* __restrict__ rm_x5, float* __restrict__ out)
{
    __shared__ float shP[256];
    __shared__ float shmn[16], shmx[16];
    const int t = threadIdx.x;
    const int lane = t & 31;
    const int wid = t >> 5;               // 0..15
    const int b = blockIdx.x;             // 0..31

    // ---- Phase A: conv2 epilogue + pool2 + block-local min/max (redundant per block,
    //      deterministic & identical across blocks -> no barrier needed before packX3)
    float cellv = 0.0f;
    if (t < 256) {
        int o = t >> 4, rem = t & 15, pr = rem >> 2, pc = rem & 3;
        float bo = b2[o];
        float m = 0.0f;
#pragma unroll
        for (int win = 0; win < 4; ++win) {
            int r = 2*pr + (win >> 1), c = 2*pc + (win & 1);
            int ham = __ldcg(&g_c2h[o*64 + r*8 + c]);
            float cnt = (float)(192000 - ham);
            float q = __fmul_rn(cnt, (1.0f/192000.0f));
            float y = __fsub_rn(__fmul_rn(2.0f, q), 1.0f);
            float v = fmaxf(__fadd_rn(__fmul_rn(y, 150.0f), bo), 0.0f);
            m = fmaxf(m, v);
        }
        shP[t] = m;
        cellv = m;
    }
    float vmn = (t < 256) ? cellv : __int_as_float(0x7f800000);
    float vmx = (t < 256) ? cellv : 0.0f;
#pragma unroll
    for (int off = 16; off; off >>= 1) {
        vmn = fminf(vmn, __shfl_xor_sync(FULLMASK, vmn, off));
        vmx = fmaxf(vmx, __shfl_xor_sync(FULLMASK, vmx, off));
    }
    if (lane == 0) { shmn[wid] = vmn; shmx[wid] = vmx; }
    __syncthreads();
    float mn2 = shmn[0], mx2 = shmx[0];
#pragma unroll
    for (int i = 1; i < 16; ++i) { mn2 = fminf(mn2, shmn[i]); mx2 = fmaxf(mx2, shmx[i]); }
    float den2 = mx2 - mn2;

    // ---- Phase B: pack X3 — 256 rows: row = b*8 + wid (wid<8)
    if (wid < 8) {
        int row = b*8 + wid;
        float pv = __fdiv_rn(shP[row] - mn2, den2);
        pack_row(rm_x3 + (size_t)row * 1280, thr_of(pv), g_X3 + row*40, lane);
    }
    gbar(FB);

    // ---- Phase C: fc3 — 120 outputs, m = wid*32 + b (wid<4, guard m<120)
    if (wid < 4) {
        int m = wid*32 + b;
        if (m < 120) {
            int h = 0;
            for (int n = lane; n < 256; n += 32) {
                const uint4* xr = reinterpret_cast<const uint4*>(g_X3 + n*40);
                const uint4* sr = reinterpret_cast<const uint4*>(g_SW3 + (m*256 + n)*40);
#pragma unroll
                for (int q = 0; q < 10; ++q) h += popc4(xr[q], sr[q]);
            }
            h = __reduce_add_sync(FULLMASK, h);
            if (lane == 0) {
                float cnt = (float)(327680 - h + __ldcg(&g_pos3[m]));   // 256*1280 - H + pos
                float q = __fmul_rn(cnt, (1.0f/328960.0f));             // 257*1280
                float o3 = __fmul_rn(__fsub_rn(__fmul_rn(2.0f, q), 1.0f), 257.0f);
                float rv = fmaxf(o3, 0.0f);
                g_f1[m] = rv;
                atomicMin(&g_mm[4], __float_as_uint(rv));
                atomicMax(&g_mm[5], __float_as_uint(rv));
            }
        }
    }
    gbar(FB);

    // ---- Phase D: pack X4 — 120 rows, row = wid*32 + b (wid<4, guard)
    if (wid < 4) {
        int row = wid*32 + b;
        if (row < 120) {
            float mn = __uint_as_float(__ldcg(&g_mm[4]));
            float mx = __uint_as_float(__ldcg(&g_mm[5]));
            float den = mx - mn;
            float pv = __fdiv_rn(__ldcg(&g_f1[row]) - mn, den);
            pack_row(rm_x4 + (size_t)row * 1280, thr_of(pv), g_X4 + row*40, lane);
        }
    }
    gbar(FB);

    // ---- Phase E: fc4 — 84 outputs, m = wid*32 + b (wid<3, guard m<84)
    if (wid < 3) {
        int m = wid*32 + b;
        if (m < 84) {
            int h = 0;
            for (int n = lane; n < 120; n += 32) {
                const uint4* xr = reinterpret_cast<const uint4*>(g_X4 + n*40);
                const uint4* sr = reinterpret_cast<const uint4*>(g_SW4 + (m*120 + n)*40);
#pragma unroll
                for (int q = 0; q < 10; ++q) h += popc4(xr[q], sr[q]);
            }
            h = __reduce_add_sync(FULLMASK, h);
            if (lane == 0) {
                float cnt = (float)(153600 - h + __ldcg(&g_pos4[m]));   // 120*1280 - H + pos
                float q = __fmul_rn(cnt, (1.0f/154880.0f));             // 121*1280
                float o4 = __fmul_rn(__fsub_rn(__fmul_rn(2.0f, q), 1.0f), 121.0f);
                float rv = fmaxf(o4, 0.0f);
                g_f2[m] = rv;
                atomicMin(&g_mm[6], __float_as_uint(rv));
                atomicMax(&g_mm[7], __float_as_uint(rv));
            }
        }
    }
    gbar(FB);

    // ---- Phase F: pack X5 — 84 rows, row = wid*32 + b (wid<3, guard)
    if (wid < 3) {
        int row = wid*32 + b;
        if (row < 84) {
            float mn = __uint_as_float(__ldcg(&g_mm[6]));
            float mx = __uint_as_float(__ldcg(&g_mm[7]));
            float den = mx - mn;
            float pv = __fdiv_rn(__ldcg(&g_f2[row]) - mn, den);
            pack_row(rm_x5 + (size_t)row * 1280, thr_of(pv), g_X5 + row*40, lane);
        }
    }
    gbar(FB);

    // ---- Phase G: fc5 — 10 outputs, m = b (warp 0 of blocks 0..9)
    if (wid == 0 && b < 10) {
        int m = b;
        int h = 0;
        for (int n = lane; n < 84; n += 32) {
            const uint4* xr = reinterpret_cast<const uint4*>(g_X5 + n*40);
            const uint4* sr = reinterpret_cast<const uint4*>(g_SW5 + (m*84 + n)*40);
#pragma unroll
            for (int q = 0; q < 10; ++q) h += popc4(xr[q], sr[q]);
        }
        h = __reduce_add_sync(FULLMASK, h);
        if (lane == 0) {
            float cnt = (float)(107520 - h + __ldcg(&g_pos5[m]));   // 84*1280 - H + pos
            float q = __fmul_rn(cnt, (1.0f/108800.0f));             // 85*1280
            out[m] = __fmul_rn(__fsub_rn(__fmul_rn(2.0f, q), 1.0f), 85.0f);
        }
    }
}

// ---------------- launch ----------------
extern "C" void kernel_launch(void* const* d_in, const int* in_sizes, int n_in,
                              void* d_out, int out_size) {
    const float* img    = (const float*)d_in[0];
    const float* w1     = (const float*)d_in[1];
    const float* b1     = (const float*)d_in[2];
    const float* w2     = (const float*)d_in[3];
    const float* b2     = (const float*)d_in[4];
    const float* wfc3   = (const float*)d_in[5];
    const float* bfc3   = (const float*)d_in[6];
    const float* wfc4   = (const float*)d_in[7];
    const float* bfc4   = (const float*)d_in[8];
    const float* wfc5   = (const float*)d_in[9];
    const float* bfc5   = (const float*)d_in[10];
    const float* rm_in1 = (const float*)d_in[11];
    const float* rm_k1  = (const float*)d_in[12];
    const float* rm_in2 = (const float*)d_in[13];
    const float* rm_k2  = (const float*)d_in[14];
    const float* rm_x3  = (const float*)d_in[15];
    const float* rm_w3  = (const float*)d_in[16];
    const float* rm_b3  = (const float*)d_in[17];
    const float* rm_x4  = (const float*)d_in[18];
    const float* rm_w4  = (const float*)d_in[19];
    const float* rm_b4  = (const float*)d_in[20];
    const float* rm_x5  = (const float*)d_in[21];
    const float* rm_w5  = (const float*)d_in[22];
    const float* rm_b5  = (const float*)d_in[23];
    float* out = (float*)d_out;

    k_pack_x1w1<<<607, 256>>>(img, w1, rm_in1, rm_k1);
    k_conv1_and_pack<<<2048, 256>>>(b1, w2, wfc3, wfc4, wfc5, bfc3, bfc4, bfc5,
                                    rm_k2, rm_w3, rm_w4, rm_w5, rm_b3, rm_b4, rm_b5);
    k_pack_X2<<<1728, 256>>>(rm_in2);
    k_conv2part<<<768, 256>>>();
    k_finish<<<FB, FT>>>(b2, rm_x3, rm_x4, rm_x5, out);
}